// round 2
// baseline (speedup 1.0000x reference)
#include <cuda_runtime.h>

#define NN 20000
#define EE 640000
#define HH 128
#define TE 64
#define NT 256
#define FP1 264   // pitch for 257-wide edge feature tile
#define FP2 132   // pitch for 128-wide intermediate tiles
#define FPN 256   // pitch for node 256-wide feature tile

// Scratch state (device globals: no allocation allowed)
__device__ float g_h[NN * HH];
__device__ float g_x[NN * 3];
__device__ float g_m[NN * HH];
__device__ float g_xacc[NN * 3];

// ---------------------------------------------------------------------------
// Tiled fp32 GEMM core: C[64,128] (+)= A[64,K] @ W[K,128]
// A in shared memory (pitch lda), W streamed global->smem in K-chunks of 8.
// 256 threads: rg=tid/16 picks 4 rows, cg=tid%16 picks 8 cols -> 4x8 acc.
// ---------------------------------------------------------------------------
__device__ __forceinline__ void mm_tile(const float* __restrict__ As, int lda,
                                        const float* __restrict__ Wg,
                                        float* Ws, int K, int tid, int rg, int cg,
                                        float acc[4][8])
{
    const int r0 = rg * 4;
    const int c0 = cg * 8;
    for (int k0 = 0; k0 < K; k0 += 8) {
        int kc = K - k0; if (kc > 8) kc = 8;
        __syncthreads();                       // protect Ws from previous use
        for (int j = tid; j < kc * 128; j += NT)
            Ws[j] = Wg[k0 * 128 + j];
        __syncthreads();
        if (kc == 8) {
#pragma unroll
            for (int q = 0; q < 2; q++) {
                float4 a4[4];
#pragma unroll
                for (int i = 0; i < 4; i++)
                    a4[i] = *(const float4*)&As[(r0 + i) * lda + k0 + q * 4];
#pragma unroll
                for (int t = 0; t < 4; t++) {
                    const float* wr = &Ws[(q * 4 + t) * 128 + c0];
                    float4 b0 = *(const float4*)wr;
                    float4 b1 = *(const float4*)(wr + 4);
                    float bv[8] = {b0.x, b0.y, b0.z, b0.w, b1.x, b1.y, b1.z, b1.w};
                    float av[4];
                    av[0] = ((const float*)&a4[0])[t];
                    av[1] = ((const float*)&a4[1])[t];
                    av[2] = ((const float*)&a4[2])[t];
                    av[3] = ((const float*)&a4[3])[t];
#pragma unroll
                    for (int i = 0; i < 4; i++)
#pragma unroll
                        for (int jj = 0; jj < 8; jj++)
                            acc[i][jj] = fmaf(av[i], bv[jj], acc[i][jj]);
                }
            }
        } else {
            for (int kk = 0; kk < kc; kk++) {
                const float* wr = &Ws[kk * 128 + c0];
                float bv[8];
#pragma unroll
                for (int jj = 0; jj < 8; jj++) bv[jj] = wr[jj];
#pragma unroll
                for (int i = 0; i < 4; i++) {
                    float a = As[(r0 + i) * lda + k0 + kk];
#pragma unroll
                    for (int jj = 0; jj < 8; jj++)
                        acc[i][jj] = fmaf(a, bv[jj], acc[i][jj]);
                }
            }
        }
    }
}

__device__ __forceinline__ void zero_acc(float acc[4][8]) {
#pragma unroll
    for (int i = 0; i < 4; i++)
#pragma unroll
        for (int j = 0; j < 8; j++) acc[i][j] = 0.0f;
}

// ---------------------------------------------------------------------------
// Fused edge pass: per 64-edge tile:
//   feat = [h[row], h[col], |x_row - x_col|^2]        (gather, smem)
//   C1   = relu(feat @ eW1 + eb1)
//   E2   = C1 @ eW2 + eb2            -> atomicAdd into g_m[row]
//   C3   = relu(E2 @ cW1 + cb1)
//   alpha= C3 @ cW2 + cb2            -> atomicAdd alpha*rel_pos into g_xacc[row]
// ---------------------------------------------------------------------------
__global__ void __launch_bounds__(NT, 2) edge_kernel(
    const int* __restrict__ ei,   // int32! (JAX default x64-disabled demotes int64)
    const float* __restrict__ eW1, const float* __restrict__ eb1,
    const float* __restrict__ eW2, const float* __restrict__ eb2,
    const float* __restrict__ cW1, const float* __restrict__ cb1,
    const float* __restrict__ cW2, const float* __restrict__ cb2)
{
    extern __shared__ float sm[];
    float* feat = sm;                       // 64*264 floats; reused for E2 (64*132)
    float* bufB = sm + TE * FP1;            // 64*132
    float* Ws   = bufB + TE * FP2;          // 8*128
    int*   srow = (int*)(Ws + 8 * 128);     // 64
    int*   scol = srow + TE;                // 64
    float* srel = (float*)(scol + TE);      // 64*3

    const int tid = threadIdx.x;
    const int e0 = blockIdx.x * TE;

    if (tid < TE) {
        int e = e0 + tid;
        int r = ei[e];
        int c = ei[EE + e];
        // defensive clamp: if indices are out of range, fail via rel_err, not IMA
        if ((unsigned)r >= NN) r = 0;
        if ((unsigned)c >= NN) c = 0;
        srow[tid] = r;
        scol[tid] = c;
        float dx = g_x[r * 3 + 0] - g_x[c * 3 + 0];
        float dy = g_x[r * 3 + 1] - g_x[c * 3 + 1];
        float dz = g_x[r * 3 + 2] - g_x[c * 3 + 2];
        srel[tid * 3 + 0] = dx; srel[tid * 3 + 1] = dy; srel[tid * 3 + 2] = dz;
        feat[tid * FP1 + 256] = dx * dx + dy * dy + dz * dz;
    }
    __syncthreads();

    // gather h[row], h[col] (float4, coalesced per edge row; L2-resident)
    for (int j = tid; j < TE * 32; j += NT) {
        int e = j >> 5, c4 = j & 31;
        const float4* hr = (const float4*)(g_h + (size_t)srow[e] * HH);
        const float4* hc = (const float4*)(g_h + (size_t)scol[e] * HH);
        *(float4*)&feat[e * FP1 + c4 * 4]       = hr[c4];
        *(float4*)&feat[e * FP1 + 128 + c4 * 4] = hc[c4];
    }
    // (mm_tile's leading __syncthreads covers the gather)

    const int rg = tid >> 4, cg = tid & 15;
    const int r0 = rg * 4, c0 = cg * 8;
    float acc[4][8];

    // GEMM1: relu(feat @ eW1 + eb1) -> bufB
    zero_acc(acc);
    mm_tile(feat, FP1, eW1, Ws, 2 * HH + 1, tid, rg, cg, acc);
    {
        float b1v[8];
#pragma unroll
        for (int jj = 0; jj < 8; jj++) b1v[jj] = eb1[c0 + jj];
#pragma unroll
        for (int i = 0; i < 4; i++)
#pragma unroll
            for (int jj = 0; jj < 8; jj++) {
                float v = acc[i][jj] + b1v[jj];
                bufB[(r0 + i) * FP2 + c0 + jj] = fmaxf(v, 0.0f);
            }
    }

    // GEMM2: E2 = bufB @ eW2 + eb2 -> scatter to m, stash in feat (reused)
    zero_acc(acc);
    mm_tile(bufB, FP2, eW2, Ws, HH, tid, rg, cg, acc);
    {
        float b2v[8];
#pragma unroll
        for (int jj = 0; jj < 8; jj++) b2v[jj] = eb2[c0 + jj];
#pragma unroll
        for (int i = 0; i < 4; i++) {
            int r = r0 + i;
            float* mrow = &g_m[(size_t)srow[r] * HH + c0];
#pragma unroll
            for (int jj = 0; jj < 8; jj++) {
                float v = acc[i][jj] + b2v[jj];
                atomicAdd(&mrow[jj], v);
                feat[r * FP2 + c0 + jj] = v;
            }
        }
    }

    // GEMM3: C3 = relu(E2 @ cW1 + cb1); alpha = C3 @ cW2 + cb2
    zero_acc(acc);
    mm_tile(feat, FP2, cW1, Ws, HH, tid, rg, cg, acc);
    {
        float w2[8], c1b[8];
#pragma unroll
        for (int jj = 0; jj < 8; jj++) { w2[jj] = cW2[c0 + jj]; c1b[jj] = cb1[c0 + jj]; }
        float part[4];
#pragma unroll
        for (int i = 0; i < 4; i++) {
            float s = 0.0f;
#pragma unroll
            for (int jj = 0; jj < 8; jj++) {
                float v = fmaxf(acc[i][jj] + c1b[jj], 0.0f);
                s = fmaf(v, w2[jj], s);
            }
            part[i] = s;
        }
#pragma unroll
        for (int off = 8; off; off >>= 1)
#pragma unroll
            for (int i = 0; i < 4; i++)
                part[i] += __shfl_down_sync(0xffffffffu, part[i], off, 16);
        if (cg == 0) {
            float cb2v = cb2[0];
#pragma unroll
            for (int i = 0; i < 4; i++) {
                int r = r0 + i;
                float alpha = part[i] + cb2v;
                int node = srow[r];
                atomicAdd(&g_xacc[node * 3 + 0], alpha * srel[r * 3 + 0]);
                atomicAdd(&g_xacc[node * 3 + 1], alpha * srel[r * 3 + 1]);
                atomicAdd(&g_xacc[node * 3 + 2], alpha * srel[r * 3 + 2]);
            }
        }
    }
}

// ---------------------------------------------------------------------------
// Node update: h += relu([h, m] @ nW1 + nb1) @ nW2 + nb2 ; x += xacc
// ---------------------------------------------------------------------------
__global__ void __launch_bounds__(NT, 2) node_kernel(
    const float* __restrict__ nW1, const float* __restrict__ nb1,
    const float* __restrict__ nW2, const float* __restrict__ nb2,
    float* __restrict__ out_h, float* __restrict__ out_x)
{
    extern __shared__ float sm[];
    float* feat = sm;                   // 64*256
    float* bufB = sm + TE * FPN;        // 64*132
    float* Ws   = bufB + TE * FP2;      // 8*128

    const int tid = threadIdx.x;
    const int n0 = blockIdx.x * TE;

    for (int j = tid; j < TE * 32; j += NT) {
        int e = j >> 5, c4 = j & 31;
        int n = n0 + e; if (n >= NN) n = NN - 1;
        *(float4*)&feat[e * FPN + c4 * 4]       = ((const float4*)(g_h + (size_t)n * HH))[c4];
        *(float4*)&feat[e * FPN + 128 + c4 * 4] = ((const float4*)(g_m + (size_t)n * HH))[c4];
    }

    const int rg = tid >> 4, cg = tid & 15;
    const int r0 = rg * 4, c0 = cg * 8;
    float acc[4][8];

    zero_acc(acc);
    mm_tile(feat, FPN, nW1, Ws, 2 * HH, tid, rg, cg, acc);
    {
        float b1v[8];
#pragma unroll
        for (int jj = 0; jj < 8; jj++) b1v[jj] = nb1[c0 + jj];
#pragma unroll
        for (int i = 0; i < 4; i++)
#pragma unroll
            for (int jj = 0; jj < 8; jj++) {
                float v = acc[i][jj] + b1v[jj];
                bufB[(r0 + i) * FP2 + c0 + jj] = fmaxf(v, 0.0f);
            }
    }

    zero_acc(acc);
    mm_tile(bufB, FP2, nW2, Ws, HH, tid, rg, cg, acc);
    {
        float b2v[8];
#pragma unroll
        for (int jj = 0; jj < 8; jj++) b2v[jj] = nb2[c0 + jj];
#pragma unroll
        for (int i = 0; i < 4; i++) {
            int n = n0 + r0 + i;
            if (n < NN) {
#pragma unroll
                for (int jj = 0; jj < 8; jj++) {
                    float hv = feat[(r0 + i) * FPN + c0 + jj] + acc[i][jj] + b2v[jj];
                    g_h[(size_t)n * HH + c0 + jj] = hv;
                    if (out_h) out_h[(size_t)n * HH + c0 + jj] = hv;
                }
            }
        }
    }

    for (int t = tid; t < TE * 3; t += NT) {
        int n = n0 + t / 3;
        if (n < NN) {
            int d = t % 3;
            float xv = g_x[n * 3 + d] + g_xacc[n * 3 + d];
            g_x[n * 3 + d] = xv;
            if (out_x) out_x[n * 3 + d] = xv;
        }
    }
}

// h0 = h_in @ emb_W + emb_b   ([N,16] @ [16,128])
__global__ void embed_kernel(const float* __restrict__ hin,
                             const float* __restrict__ W,
                             const float* __restrict__ b)
{
    int j = blockIdx.x * blockDim.x + threadIdx.x;
    if (j >= NN * HH) return;
    int n = j >> 7, c = j & 127;
    float acc = b[c];
#pragma unroll
    for (int k = 0; k < 16; k++)
        acc = fmaf(hin[n * 16 + k], W[k * 128 + c], acc);
    g_h[j] = acc;
}

__global__ void xcopy_kernel(const float* __restrict__ xin)
{
    int i = blockIdx.x * blockDim.x + threadIdx.x;
    if (i < NN * 3) g_x[i] = xin[i];
}

__global__ void zero_kernel()
{
    int i = blockIdx.x * blockDim.x + threadIdx.x;
    if (i < NN * HH) g_m[i] = 0.0f;
    if (i < NN * 3) g_xacc[i] = 0.0f;
}

extern "C" void kernel_launch(void* const* d_in, const int* in_sizes, int n_in,
                              void* d_out, int out_size)
{
    const float* h_in  = (const float*)d_in[0];
    const float* x_in  = (const float*)d_in[1];
    const int*   ei    = (const int*)d_in[2];    // int32 (JAX x64 disabled)
    const float* emb_W = (const float*)d_in[3];
    const float* emb_b = (const float*)d_in[4];
    const float* eW1   = (const float*)d_in[5];
    const float* eb1   = (const float*)d_in[6];
    const float* eW2   = (const float*)d_in[7];
    const float* eb2   = (const float*)d_in[8];
    const float* nW1   = (const float*)d_in[9];
    const float* nb1   = (const float*)d_in[10];
    const float* nW2   = (const float*)d_in[11];
    const float* nb2   = (const float*)d_in[12];
    const float* cW1   = (const float*)d_in[13];
    const float* cb1   = (const float*)d_in[14];
    const float* cW2   = (const float*)d_in[15];
    const float* cb2   = (const float*)d_in[16];
    float* out = (float*)d_out;

    const int EDGE_SMEM = (TE * FP1 + TE * FP2 + 8 * 128) * 4 + TE * 4 * 2 + TE * 3 * 4;
    const int NODE_SMEM = (TE * FPN + TE * FP2 + 8 * 128) * 4;

    cudaFuncSetAttribute(edge_kernel, cudaFuncAttributeMaxDynamicSharedMemorySize, EDGE_SMEM);
    cudaFuncSetAttribute(node_kernel, cudaFuncAttributeMaxDynamicSharedMemorySize, NODE_SMEM);

    xcopy_kernel<<<(NN * 3 + 255) / 256, 256>>>(x_in);
    embed_kernel<<<(NN * HH + 255) / 256, 256>>>(h_in, emb_W, emb_b);

    for (int l = 0; l < 2; l++) {
        zero_kernel<<<(NN * HH + 255) / 256, 256>>>();
        edge_kernel<<<EE / TE, NT, EDGE_SMEM>>>(ei, eW1, eb1, eW2, eb2, cW1, cb1, cW2, cb2);
        bool fin = (l == 1);
        node_kernel<<<(NN + TE - 1) / TE, NT, NODE_SMEM>>>(
            nW1, nb1, nW2, nb2,
            fin ? out : (float*)nullptr,
            fin ? out + (size_t)NN * HH : (float*)nullptr);
    }
}

// round 3
// speedup vs baseline: 3.8912x; 3.8912x over previous
#include <cuda_runtime.h>
#include <cstdint>

#define NN 20000
#define EE 640000
#define HH 128
#define TE 64
#define NT 256
#define FP2 132   // pitch for node kernel intermediate tiles
#define FPN 256   // pitch for node 256-wide feature tile

// Scratch state (device globals: no allocation allowed)
__device__ float g_h[NN * HH];
__device__ float g_x[NN * 3];
__device__ float g_m[NN * HH];
__device__ float g_xacc[NN * 3];

// ===========================================================================
// tf32 helpers
// ===========================================================================
__device__ __forceinline__ float to_tf32(float x) {
    uint32_t r;
    asm("cvt.rna.tf32.f32 %0, %1;" : "=r"(r) : "f"(x));
    return __uint_as_float(r);
}

__device__ __forceinline__ void mma8(float* c,
                                     uint32_t a0, uint32_t a1, uint32_t a2, uint32_t a3,
                                     uint32_t b0, uint32_t b1) {
    asm volatile(
        "mma.sync.aligned.m16n8k8.row.col.f32.tf32.tf32.f32 "
        "{%0,%1,%2,%3}, {%4,%5,%6,%7}, {%8,%9}, {%0,%1,%2,%3};"
        : "+f"(c[0]), "+f"(c[1]), "+f"(c[2]), "+f"(c[3])
        : "r"(a0), "r"(a1), "r"(a2), "r"(a3), "r"(b0), "r"(b1));
}

// ===========================================================================
// Edge kernel smem layout (floats). Total 22400 floats = 89600 B.
// ===========================================================================
#define PA 132            // A-tile pitch: (4r+c)%32 distinct -> conflict-free frags
#define PW 136            // W-chunk pitch: (8k+n)%32 distinct -> conflict-free frags
#define S_AROW 0                          // 64*132 = 8448  (h[row] tf32; reused as E2)
#define S_ACOL (S_AROW + TE * PA)         // 8448           (h[col] tf32; reused as C1)
#define S_WBUF (S_ACOL + TE * PA)         // 2*16*136 = 4352
#define S_EB1  (S_WBUF + 2 * 16 * PW)     // 128
#define S_EB2  (S_EB1 + 128)
#define S_CB1  (S_EB2 + 128)
#define S_CW2  (S_CB1 + 128)
#define S_W1L  (S_CW2 + 128)              // eW1 row 256
#define S_SROW (S_W1L + 128)              // int[64]
#define S_SCOL (S_SROW + 64)              // int[64]
#define S_SREL (S_SCOL + 64)              // 64*3
#define S_SRD  (S_SREL + 192)             // 64
#define S_PART (S_SRD + 64)               // 64*2
#define S_TOT  (S_PART + 128)
#define EDGE_SMEM_BYTES (S_TOT * 4)

// ---------------------------------------------------------------------------
// One K=128 GEMM pass: acc[8][4] += As[64,128] @ Wg[128,128]
// As in smem (tf32, pitch PA). Wg global, streamed double-buffered in
// 16-row chunks into Wbuf (tf32, pitch PW). One __syncthreads per chunk.
// Warp tile: 16 rows (m_base) x 64 cols (n_base), 8 m16n8k8 tiles.
// ---------------------------------------------------------------------------
__device__ __forceinline__ void gemm_pass(const float* __restrict__ As,
                                          const float* __restrict__ Wg,
                                          float* __restrict__ Wbuf,
                                          float acc[8][4],
                                          int tid, int lane, int m_base, int n_base)
{
    const int g = lane >> 2, t = lane & 3;
    const int i0 = tid, i1 = tid + 256;          // float4 indices into 16x128 chunk

    float4 pre0 = ((const float4*)Wg)[i0];
    float4 pre1 = ((const float4*)Wg)[i1];
    {
        float* d0 = Wbuf + (i0 >> 5) * PW + (i0 & 31) * 4;
        float* d1 = Wbuf + (i1 >> 5) * PW + (i1 & 31) * 4;
        *(float4*)d0 = make_float4(to_tf32(pre0.x), to_tf32(pre0.y), to_tf32(pre0.z), to_tf32(pre0.w));
        *(float4*)d1 = make_float4(to_tf32(pre1.x), to_tf32(pre1.y), to_tf32(pre1.z), to_tf32(pre1.w));
    }
    __syncthreads();

    for (int ch = 0; ch < 8; ch++) {
        const int cur = ch & 1;
        if (ch < 7) {
            const float4* src = (const float4*)(Wg + (ch + 1) * 2048);
            pre0 = src[i0];
            pre1 = src[i1];
        }
        const uint32_t* Wc = (const uint32_t*)(Wbuf + cur * (16 * PW));
#pragma unroll
        for (int ks = 0; ks < 2; ks++) {
            const uint32_t* Ab = (const uint32_t*)As + (m_base + g) * PA + ch * 16 + ks * 8 + t;
            uint32_t a0 = Ab[0];
            uint32_t a1 = Ab[8 * PA];
            uint32_t a2 = Ab[4];
            uint32_t a3 = Ab[8 * PA + 4];
            const uint32_t* Bb = Wc + (ks * 8 + t) * PW + n_base + g;
#pragma unroll
            for (int tt = 0; tt < 8; tt++) {
                uint32_t b0 = Bb[tt * 8];
                uint32_t b1 = Bb[4 * PW + tt * 8];
                mma8(acc[tt], a0, a1, a2, a3, b0, b1);
            }
        }
        if (ch < 7) {
            float* dst = Wbuf + (cur ^ 1) * (16 * PW);
            float* d0 = dst + (i0 >> 5) * PW + (i0 & 31) * 4;
            float* d1 = dst + (i1 >> 5) * PW + (i1 & 31) * 4;
            *(float4*)d0 = make_float4(to_tf32(pre0.x), to_tf32(pre0.y), to_tf32(pre0.z), to_tf32(pre0.w));
            *(float4*)d1 = make_float4(to_tf32(pre1.x), to_tf32(pre1.y), to_tf32(pre1.z), to_tf32(pre1.w));
        }
        __syncthreads();
    }
}

__device__ __forceinline__ void zero8(float acc[8][4]) {
#pragma unroll
    for (int i = 0; i < 8; i++)
#pragma unroll
        for (int j = 0; j < 4; j++) acc[i][j] = 0.0f;
}

// ---------------------------------------------------------------------------
// Fused edge pass (tensor-core tf32). Per 64-edge tile:
//   C1   = relu([h_row|h_col|rd] @ eW1 + eb1)     (split-K + rank-1 epilogue)
//   E2   = C1 @ eW2 + eb2      -> atomicAdd into g_m[row]
//   alpha= relu(E2 @ cW1 + cb1) @ cW2 + cb2 -> atomicAdd alpha*rel into g_xacc
// ---------------------------------------------------------------------------
__global__ void __launch_bounds__(NT, 2) edge_kernel(
    const int* __restrict__ ei,
    const float* __restrict__ eW1, const float* __restrict__ eb1,
    const float* __restrict__ eW2, const float* __restrict__ eb2,
    const float* __restrict__ cW1, const float* __restrict__ cb1,
    const float* __restrict__ cW2, const float* __restrict__ cb2)
{
    extern __shared__ float sm[];
    float* Arow = sm + S_AROW;
    float* Acol = sm + S_ACOL;          // becomes C1
    float* Wbuf = sm + S_WBUF;
    int*   srow = (int*)(sm + S_SROW);
    int*   scol = (int*)(sm + S_SCOL);
    float* srel = sm + S_SREL;
    float* srd  = sm + S_SRD;
    float* spart= sm + S_PART;

    const int tid  = threadIdx.x;
    const int lane = tid & 31;
    const int wid  = tid >> 5;
    const int wm   = wid & 3;           // 4 M-warps
    const int wn   = wid >> 2;          // 2 N-warps
    const int m_base = wm * 16;
    const int n_base = wn * 64;
    const int g = lane >> 2, t = lane & 3;
    const int e0 = blockIdx.x * TE;

    if (tid < TE) {
        int e = e0 + tid;
        int r = ei[e];
        int c = ei[EE + e];
        if ((unsigned)r >= NN) r = 0;
        if ((unsigned)c >= NN) c = 0;
        srow[tid] = r;
        scol[tid] = c;
        float dx = g_x[r * 3 + 0] - g_x[c * 3 + 0];
        float dy = g_x[r * 3 + 1] - g_x[c * 3 + 1];
        float dz = g_x[r * 3 + 2] - g_x[c * 3 + 2];
        srel[tid * 3 + 0] = dx; srel[tid * 3 + 1] = dy; srel[tid * 3 + 2] = dz;
        srd[tid] = dx * dx + dy * dy + dz * dz;
    }
    if (tid < 128) {
        sm[S_EB1 + tid] = eb1[tid];
        sm[S_EB2 + tid] = eb2[tid];
        sm[S_CB1 + tid] = cb1[tid];
        sm[S_CW2 + tid] = cW2[tid];
        sm[S_W1L + tid] = eW1[256 * 128 + tid];
    }
    __syncthreads();

    // gather h[row], h[col] into tf32 smem tiles (L2-resident)
    for (int j = tid; j < TE * 32; j += NT) {
        int e = j >> 5, c4 = j & 31;
        float4 hr = ((const float4*)(g_h + (size_t)srow[e] * HH))[c4];
        float4 hc = ((const float4*)(g_h + (size_t)scol[e] * HH))[c4];
        *(float4*)&Arow[e * PA + c4 * 4] =
            make_float4(to_tf32(hr.x), to_tf32(hr.y), to_tf32(hr.z), to_tf32(hr.w));
        *(float4*)&Acol[e * PA + c4 * 4] =
            make_float4(to_tf32(hc.x), to_tf32(hc.y), to_tf32(hc.z), to_tf32(hc.w));
    }
    // (gemm_pass's first __syncthreads covers the gather)

    float acc[8][4];

    // ---- GEMM1: h_row @ W1[0:128] + h_col @ W1[128:256] ----
    zero8(acc);
    gemm_pass(Arow, eW1,              Wbuf, acc, tid, lane, m_base, n_base);
    gemm_pass(Acol, eW1 + 128 * 128,  Wbuf, acc, tid, lane, m_base, n_base);

    // epilogue 1: + rd*w1_last + bias, relu, tf32 -> C1 (Acol reuse; safe after sync)
    {
        const int r0 = m_base + g, r1 = r0 + 8;
        float d0 = srd[r0], d1 = srd[r1];
#pragma unroll
        for (int tt = 0; tt < 8; tt++) {
            int c = n_base + tt * 8 + t * 2;
            float bA = sm[S_EB1 + c], bB = sm[S_EB1 + c + 1];
            float wA = sm[S_W1L + c], wB = sm[S_W1L + c + 1];
            Acol[r0 * PA + c]     = to_tf32(fmaxf(acc[tt][0] + bA + d0 * wA, 0.0f));
            Acol[r0 * PA + c + 1] = to_tf32(fmaxf(acc[tt][1] + bB + d0 * wB, 0.0f));
            Acol[r1 * PA + c]     = to_tf32(fmaxf(acc[tt][2] + bA + d1 * wA, 0.0f));
            Acol[r1 * PA + c + 1] = to_tf32(fmaxf(acc[tt][3] + bB + d1 * wB, 0.0f));
        }
    }

    // ---- GEMM2: E2 = C1 @ eW2 ----  (gemm_pass's first sync orders C1 writes)
    zero8(acc);
    gemm_pass(Acol, eW2, Wbuf, acc, tid, lane, m_base, n_base);

    // epilogue 2: +bias -> atomic scatter to g_m[row], tf32 stash -> E2 (Arow reuse)
    {
        const int r0 = m_base + g, r1 = r0 + 8;
        float* m0 = g_m + (size_t)srow[r0] * HH;
        float* m1 = g_m + (size_t)srow[r1] * HH;
#pragma unroll
        for (int tt = 0; tt < 8; tt++) {
            int c = n_base + tt * 8 + t * 2;
            float bA = sm[S_EB2 + c], bB = sm[S_EB2 + c + 1];
            float v00 = acc[tt][0] + bA, v01 = acc[tt][1] + bB;
            float v10 = acc[tt][2] + bA, v11 = acc[tt][3] + bB;
            atomicAdd(&m0[c], v00);  atomicAdd(&m0[c + 1], v01);
            atomicAdd(&m1[c], v10);  atomicAdd(&m1[c + 1], v11);
            Arow[r0 * PA + c]     = to_tf32(v00);
            Arow[r0 * PA + c + 1] = to_tf32(v01);
            Arow[r1 * PA + c]     = to_tf32(v10);
            Arow[r1 * PA + c + 1] = to_tf32(v11);
        }
    }

    // ---- GEMM3: C3 = relu(E2 @ cW1 + cb1); alpha = C3 @ cW2 + cb2 ----
    zero8(acc);
    gemm_pass(Arow, cW1, Wbuf, acc, tid, lane, m_base, n_base);
    {
        float p0 = 0.0f, p1 = 0.0f;
#pragma unroll
        for (int tt = 0; tt < 8; tt++) {
            int c = n_base + tt * 8 + t * 2;
            float bA = sm[S_CB1 + c], bB = sm[S_CB1 + c + 1];
            float wA = sm[S_CW2 + c], wB = sm[S_CW2 + c + 1];
            p0 = fmaf(fmaxf(acc[tt][0] + bA, 0.0f), wA, p0);
            p0 = fmaf(fmaxf(acc[tt][1] + bB, 0.0f), wB, p0);
            p1 = fmaf(fmaxf(acc[tt][2] + bA, 0.0f), wA, p1);
            p1 = fmaf(fmaxf(acc[tt][3] + bB, 0.0f), wB, p1);
        }
        p0 += __shfl_xor_sync(0xffffffffu, p0, 1);
        p0 += __shfl_xor_sync(0xffffffffu, p0, 2);
        p1 += __shfl_xor_sync(0xffffffffu, p1, 1);
        p1 += __shfl_xor_sync(0xffffffffu, p1, 2);
        if (t == 0) {
            spart[(m_base + g) * 2 + wn]     = p0;
            spart[(m_base + g + 8) * 2 + wn] = p1;
        }
    }
    __syncthreads();

    if (tid < TE) {
        float alpha = spart[tid * 2] + spart[tid * 2 + 1] + cb2[0];
        int node = srow[tid];
        atomicAdd(&g_xacc[node * 3 + 0], alpha * srel[tid * 3 + 0]);
        atomicAdd(&g_xacc[node * 3 + 1], alpha * srel[tid * 3 + 1]);
        atomicAdd(&g_xacc[node * 3 + 2], alpha * srel[tid * 3 + 2]);
    }
}

// ===========================================================================
// Scalar node-side machinery (3% of FLOPs; unchanged from passing R2 kernel)
// ===========================================================================
__device__ __forceinline__ void mm_tile(const float* __restrict__ As, int lda,
                                        const float* __restrict__ Wg,
                                        float* Ws, int K, int tid, int rg, int cg,
                                        float acc[4][8])
{
    const int r0 = rg * 4;
    const int c0 = cg * 8;
    for (int k0 = 0; k0 < K; k0 += 8) {
        int kc = K - k0; if (kc > 8) kc = 8;
        __syncthreads();
        for (int j = tid; j < kc * 128; j += NT)
            Ws[j] = Wg[k0 * 128 + j];
        __syncthreads();
#pragma unroll
        for (int q = 0; q < 2; q++) {
            float4 a4[4];
#pragma unroll
            for (int i = 0; i < 4; i++)
                a4[i] = *(const float4*)&As[(r0 + i) * lda + k0 + q * 4];
#pragma unroll
            for (int tt = 0; tt < 4; tt++) {
                const float* wr = &Ws[(q * 4 + tt) * 128 + c0];
                float4 b0 = *(const float4*)wr;
                float4 b1 = *(const float4*)(wr + 4);
                float bv[8] = {b0.x, b0.y, b0.z, b0.w, b1.x, b1.y, b1.z, b1.w};
                float av[4];
                av[0] = ((const float*)&a4[0])[tt];
                av[1] = ((const float*)&a4[1])[tt];
                av[2] = ((const float*)&a4[2])[tt];
                av[3] = ((const float*)&a4[3])[tt];
#pragma unroll
                for (int i = 0; i < 4; i++)
#pragma unroll
                    for (int jj = 0; jj < 8; jj++)
                        acc[i][jj] = fmaf(av[i], bv[jj], acc[i][jj]);
            }
        }
    }
}

__device__ __forceinline__ void zero_acc(float acc[4][8]) {
#pragma unroll
    for (int i = 0; i < 4; i++)
#pragma unroll
        for (int j = 0; j < 8; j++) acc[i][j] = 0.0f;
}

__global__ void __launch_bounds__(NT, 2) node_kernel(
    const float* __restrict__ nW1, const float* __restrict__ nb1,
    const float* __restrict__ nW2, const float* __restrict__ nb2,
    float* __restrict__ out_h, float* __restrict__ out_x)
{
    extern __shared__ float sm[];
    float* feat = sm;                   // 64*256
    float* bufB = sm + TE * FPN;        // 64*132
    float* Ws   = bufB + TE * FP2;      // 8*128

    const int tid = threadIdx.x;
    const int n0 = blockIdx.x * TE;

    for (int j = tid; j < TE * 32; j += NT) {
        int e = j >> 5, c4 = j & 31;
        int n = n0 + e; if (n >= NN) n = NN - 1;
        *(float4*)&feat[e * FPN + c4 * 4]       = ((const float4*)(g_h + (size_t)n * HH))[c4];
        *(float4*)&feat[e * FPN + 128 + c4 * 4] = ((const float4*)(g_m + (size_t)n * HH))[c4];
    }

    const int rg = tid >> 4, cg = tid & 15;
    const int r0 = rg * 4, c0 = cg * 8;
    float acc[4][8];

    zero_acc(acc);
    mm_tile(feat, FPN, nW1, Ws, 2 * HH, tid, rg, cg, acc);
    {
        float b1v[8];
#pragma unroll
        for (int jj = 0; jj < 8; jj++) b1v[jj] = nb1[c0 + jj];
#pragma unroll
        for (int i = 0; i < 4; i++)
#pragma unroll
            for (int jj = 0; jj < 8; jj++) {
                float v = acc[i][jj] + b1v[jj];
                bufB[(r0 + i) * FP2 + c0 + jj] = fmaxf(v, 0.0f);
            }
    }

    zero_acc(acc);
    mm_tile(bufB, FP2, nW2, Ws, HH, tid, rg, cg, acc);
    {
        float b2v[8];
#pragma unroll
        for (int jj = 0; jj < 8; jj++) b2v[jj] = nb2[c0 + jj];
#pragma unroll
        for (int i = 0; i < 4; i++) {
            int n = n0 + r0 + i;
            if (n < NN) {
#pragma unroll
                for (int jj = 0; jj < 8; jj++) {
                    float hv = feat[(r0 + i) * FPN + c0 + jj] + acc[i][jj] + b2v[jj];
                    g_h[(size_t)n * HH + c0 + jj] = hv;
                    if (out_h) out_h[(size_t)n * HH + c0 + jj] = hv;
                }
            }
        }
    }

    for (int t = tid; t < TE * 3; t += NT) {
        int n = n0 + t / 3;
        if (n < NN) {
            int d = t % 3;
            float xv = g_x[n * 3 + d] + g_xacc[n * 3 + d];
            g_x[n * 3 + d] = xv;
            if (out_x) out_x[n * 3 + d] = xv;
        }
    }
}

__global__ void embed_kernel(const float* __restrict__ hin,
                             const float* __restrict__ W,
                             const float* __restrict__ b)
{
    int j = blockIdx.x * blockDim.x + threadIdx.x;
    if (j >= NN * HH) return;
    int n = j >> 7, c = j & 127;
    float acc = b[c];
#pragma unroll
    for (int k = 0; k < 16; k++)
        acc = fmaf(hin[n * 16 + k], W[k * 128 + c], acc);
    g_h[j] = acc;
}

__global__ void xcopy_kernel(const float* __restrict__ xin)
{
    int i = blockIdx.x * blockDim.x + threadIdx.x;
    if (i < NN * 3) g_x[i] = xin[i];
}

__global__ void zero_kernel()
{
    int i = blockIdx.x * blockDim.x + threadIdx.x;
    if (i < NN * HH) g_m[i] = 0.0f;
    if (i < NN * 3) g_xacc[i] = 0.0f;
}

extern "C" void kernel_launch(void* const* d_in, const int* in_sizes, int n_in,
                              void* d_out, int out_size)
{
    const float* h_in  = (const float*)d_in[0];
    const float* x_in  = (const float*)d_in[1];
    const int*   ei    = (const int*)d_in[2];
    const float* emb_W = (const float*)d_in[3];
    const float* emb_b = (const float*)d_in[4];
    const float* eW1   = (const float*)d_in[5];
    const float* eb1   = (const float*)d_in[6];
    const float* eW2   = (const float*)d_in[7];
    const float* eb2   = (const float*)d_in[8];
    const float* nW1   = (const float*)d_in[9];
    const float* nb1   = (const float*)d_in[10];
    const float* nW2   = (const float*)d_in[11];
    const float* nb2   = (const float*)d_in[12];
    const float* cW1   = (const float*)d_in[13];
    const float* cb1   = (const float*)d_in[14];
    const float* cW2   = (const float*)d_in[15];
    const float* cb2   = (const float*)d_in[16];
    float* out = (float*)d_out;

    const int NODE_SMEM = (TE * FPN + TE * FP2 + 8 * 128) * 4;

    cudaFuncSetAttribute(edge_kernel, cudaFuncAttributeMaxDynamicSharedMemorySize, EDGE_SMEM_BYTES);
    cudaFuncSetAttribute(node_kernel, cudaFuncAttributeMaxDynamicSharedMemorySize, NODE_SMEM);

    xcopy_kernel<<<(NN * 3 + 255) / 256, 256>>>(x_in);
    embed_kernel<<<(NN * HH + 255) / 256, 256>>>(h_in, emb_W, emb_b);

    for (int l = 0; l < 2; l++) {
        zero_kernel<<<(NN * HH + 255) / 256, 256>>>();
        edge_kernel<<<EE / TE, NT, EDGE_SMEM_BYTES>>>(ei, eW1, eb1, eW2, eb2, cW1, cb1, cW2, cb2);
        bool fin = (l == 1);
        node_kernel<<<(NN + TE - 1) / TE, NT, NODE_SMEM>>>(
            nW1, nb1, nW2, nb2,
            fin ? out : (float*)nullptr,
            fin ? out + (size_t)NN * HH : (float*)nullptr);
    }
}

// round 4
// speedup vs baseline: 4.1326x; 1.0620x over previous
#include <cuda_runtime.h>
#include <cstdint>

#define NN 20000
#define EE 640000
#define HH 128
#define TE 128          // edges per block (edge kernel)
#define NT 256
#define TN 64           // nodes per block (node kernel)
#define FP2 132
#define FPN 256

// Scratch state (device globals: no allocation allowed)
__device__ float g_h[NN * HH];
__device__ float g_x[NN * 3];
__device__ float g_m[NN * HH];
__device__ float g_xacc[NN * 3];

// ===========================================================================
// tf32 helpers
// ===========================================================================
__device__ __forceinline__ float to_tf32(float x) {
    uint32_t r;
    asm("cvt.rna.tf32.f32 %0, %1;" : "=r"(r) : "f"(x));
    return __uint_as_float(r);
}

__device__ __forceinline__ void mma8(float* c,
                                     uint32_t a0, uint32_t a1, uint32_t a2, uint32_t a3,
                                     uint32_t b0, uint32_t b1) {
    asm volatile(
        "mma.sync.aligned.m16n8k8.row.col.f32.tf32.tf32.f32 "
        "{%0,%1,%2,%3}, {%4,%5,%6,%7}, {%8,%9}, {%0,%1,%2,%3};"
        : "+f"(c[0]), "+f"(c[1]), "+f"(c[2]), "+f"(c[3])
        : "r"(a0), "r"(a1), "r"(a2), "r"(a3), "r"(b0), "r"(b1));
}

// ===========================================================================
// Edge kernel smem layout (floats). 128-edge tile. Total 39808 fl = 159232 B.
// ===========================================================================
#define PA 132            // A-tile pitch (conflict-free frag reads)
#define PW 136            // W-chunk pitch (conflict-free frag reads)
#define S_AROW 0                          // 128*132 (h[row] tf32; reused as E2)
#define S_ACOL (S_AROW + TE * PA)         // 128*132 (h[col] tf32; reused as C1)
#define S_WBUF (S_ACOL + TE * PA)         // 2*16*136
#define S_EB1  (S_WBUF + 2 * 16 * PW)
#define S_EB2  (S_EB1 + 128)
#define S_CB1  (S_EB2 + 128)
#define S_CW2  (S_CB1 + 128)
#define S_W1L  (S_CW2 + 128)              // eW1 row 256
#define S_SROW (S_W1L + 128)              // int[128]
#define S_SCOL (S_SROW + TE)              // int[128]
#define S_SREL (S_SCOL + TE)              // 128*3
#define S_SRD  (S_SREL + TE * 3)          // 128
#define S_PART (S_SRD + TE)               // 128*2
#define S_TOT  (S_PART + TE * 2)
#define EDGE_SMEM_BYTES (S_TOT * 4)

// ---------------------------------------------------------------------------
// One K=128 GEMM pass: acc[2][8][4] += As[128,128] @ Wg[128,128] (warp slice).
// As in smem (tf32, pitch PA). Wg streamed double-buffered in 16-row chunks.
// Warp tile: 32 rows (m_base, 2 m16 tiles) x 64 cols (n_base, 8 n8 tiles).
// B fragments loaded once per (ks,tt) and reused across both m16 tiles.
// ---------------------------------------------------------------------------
__device__ __forceinline__ void gemm_pass(const float* __restrict__ As,
                                          const float* __restrict__ Wg,
                                          float* __restrict__ Wbuf,
                                          float acc[2][8][4],
                                          int tid, int lane, int m_base, int n_base)
{
    const int g = lane >> 2, t = lane & 3;
    const int i0 = tid, i1 = tid + 256;          // float4 indices into 16x128 chunk

    float4 pre0 = ((const float4*)Wg)[i0];
    float4 pre1 = ((const float4*)Wg)[i1];
    {
        float* d0 = Wbuf + (i0 >> 5) * PW + (i0 & 31) * 4;
        float* d1 = Wbuf + (i1 >> 5) * PW + (i1 & 31) * 4;
        *(float4*)d0 = make_float4(to_tf32(pre0.x), to_tf32(pre0.y), to_tf32(pre0.z), to_tf32(pre0.w));
        *(float4*)d1 = make_float4(to_tf32(pre1.x), to_tf32(pre1.y), to_tf32(pre1.z), to_tf32(pre1.w));
    }
    __syncthreads();

    for (int ch = 0; ch < 8; ch++) {
        const int cur = ch & 1;
        if (ch < 7) {
            const float4* src = (const float4*)(Wg + (ch + 1) * 2048);
            pre0 = src[i0];
            pre1 = src[i1];
        }
        const uint32_t* Wc = (const uint32_t*)(Wbuf + cur * (16 * PW));
#pragma unroll
        for (int ks = 0; ks < 2; ks++) {
            const uint32_t* A0 = (const uint32_t*)As + (m_base + g) * PA + ch * 16 + ks * 8 + t;
            const uint32_t* A1 = A0 + 16 * PA;
            uint32_t a00 = A0[0], a01 = A0[8 * PA], a02 = A0[4], a03 = A0[8 * PA + 4];
            uint32_t a10 = A1[0], a11 = A1[8 * PA], a12 = A1[4], a13 = A1[8 * PA + 4];
            const uint32_t* Bb = Wc + (ks * 8 + t) * PW + n_base + g;
#pragma unroll
            for (int tt = 0; tt < 8; tt++) {
                uint32_t b0 = Bb[tt * 8];
                uint32_t b1 = Bb[4 * PW + tt * 8];
                mma8(acc[0][tt], a00, a01, a02, a03, b0, b1);
                mma8(acc[1][tt], a10, a11, a12, a13, b0, b1);
            }
        }
        if (ch < 7) {
            float* dst = Wbuf + (cur ^ 1) * (16 * PW);
            float* d0 = dst + (i0 >> 5) * PW + (i0 & 31) * 4;
            float* d1 = dst + (i1 >> 5) * PW + (i1 & 31) * 4;
            *(float4*)d0 = make_float4(to_tf32(pre0.x), to_tf32(pre0.y), to_tf32(pre0.z), to_tf32(pre0.w));
            *(float4*)d1 = make_float4(to_tf32(pre1.x), to_tf32(pre1.y), to_tf32(pre1.z), to_tf32(pre1.w));
        }
        __syncthreads();
    }
}

__device__ __forceinline__ void zero8(float acc[2][8][4]) {
#pragma unroll
    for (int m = 0; m < 2; m++)
#pragma unroll
        for (int i = 0; i < 8; i++)
#pragma unroll
            for (int j = 0; j < 4; j++) acc[m][i][j] = 0.0f;
}

// ---------------------------------------------------------------------------
// Fused edge pass (tf32 tensor cores). Per 128-edge tile:
//   C1   = relu([h_row|h_col|rd] @ eW1 + eb1)
//   E2   = C1 @ eW2 + eb2      -> atomicAdd into g_m[row]
//   alpha= relu(E2 @ cW1 + cb1) @ cW2 + cb2 -> atomicAdd alpha*rel into g_xacc
// ---------------------------------------------------------------------------
__global__ void __launch_bounds__(NT, 1) edge_kernel(
    const int* __restrict__ ei,
    const float* __restrict__ eW1, const float* __restrict__ eb1,
    const float* __restrict__ eW2, const float* __restrict__ eb2,
    const float* __restrict__ cW1, const float* __restrict__ cb1,
    const float* __restrict__ cW2, const float* __restrict__ cb2)
{
    extern __shared__ float sm[];
    float* Arow = sm + S_AROW;
    float* Acol = sm + S_ACOL;          // becomes C1
    float* Wbuf = sm + S_WBUF;
    int*   srow = (int*)(sm + S_SROW);
    int*   scol = (int*)(sm + S_SCOL);
    float* srel = sm + S_SREL;
    float* srd  = sm + S_SRD;
    float* spart= sm + S_PART;

    const int tid  = threadIdx.x;
    const int lane = tid & 31;
    const int wid  = tid >> 5;
    const int wm   = wid & 3;           // 4 M-warp-groups of 32 rows
    const int wn   = wid >> 2;          // 2 N-warp-groups of 64 cols
    const int m_base = wm * 32;
    const int n_base = wn * 64;
    const int g = lane >> 2, t = lane & 3;
    const int e0 = blockIdx.x * TE;

    if (tid < TE) {
        int e = e0 + tid;
        int r = ei[e];
        int c = ei[EE + e];
        if ((unsigned)r >= NN) r = 0;
        if ((unsigned)c >= NN) c = 0;
        srow[tid] = r;
        scol[tid] = c;
        float dx = g_x[r * 3 + 0] - g_x[c * 3 + 0];
        float dy = g_x[r * 3 + 1] - g_x[c * 3 + 1];
        float dz = g_x[r * 3 + 2] - g_x[c * 3 + 2];
        srel[tid * 3 + 0] = dx; srel[tid * 3 + 1] = dy; srel[tid * 3 + 2] = dz;
        srd[tid] = dx * dx + dy * dy + dz * dz;
    }
    if (tid < 128) {
        sm[S_EB1 + tid] = eb1[tid];
        sm[S_EB2 + tid] = eb2[tid];
        sm[S_CB1 + tid] = cb1[tid];
        sm[S_CW2 + tid] = cW2[tid];
        sm[S_W1L + tid] = eW1[256 * 128 + tid];
    }
    __syncthreads();

    // gather h[row], h[col] into tf32 smem tiles (L2-resident)
    for (int j = tid; j < TE * 32; j += NT) {
        int e = j >> 5, c4 = j & 31;
        float4 hr = ((const float4*)(g_h + (size_t)srow[e] * HH))[c4];
        float4 hc = ((const float4*)(g_h + (size_t)scol[e] * HH))[c4];
        *(float4*)&Arow[e * PA + c4 * 4] =
            make_float4(to_tf32(hr.x), to_tf32(hr.y), to_tf32(hr.z), to_tf32(hr.w));
        *(float4*)&Acol[e * PA + c4 * 4] =
            make_float4(to_tf32(hc.x), to_tf32(hc.y), to_tf32(hc.z), to_tf32(hc.w));
    }
    // (gemm_pass's first __syncthreads covers the gather)

    float acc[2][8][4];

    // ---- GEMM1: h_row @ W1[0:128] + h_col @ W1[128:256] ----
    zero8(acc);
    gemm_pass(Arow, eW1,             Wbuf, acc, tid, lane, m_base, n_base);
    gemm_pass(Acol, eW1 + 128 * 128, Wbuf, acc, tid, lane, m_base, n_base);

    // epilogue 1: + rd*w1_last + bias, relu, tf32 -> C1 (Acol reuse)
#pragma unroll
    for (int mg = 0; mg < 2; mg++) {
        const int r0 = m_base + mg * 16 + g, r1 = r0 + 8;
        float d0 = srd[r0], d1 = srd[r1];
#pragma unroll
        for (int tt = 0; tt < 8; tt++) {
            int c = n_base + tt * 8 + t * 2;
            float bA = sm[S_EB1 + c], bB = sm[S_EB1 + c + 1];
            float wA = sm[S_W1L + c], wB = sm[S_W1L + c + 1];
            Acol[r0 * PA + c]     = to_tf32(fmaxf(acc[mg][tt][0] + bA + d0 * wA, 0.0f));
            Acol[r0 * PA + c + 1] = to_tf32(fmaxf(acc[mg][tt][1] + bB + d0 * wB, 0.0f));
            Acol[r1 * PA + c]     = to_tf32(fmaxf(acc[mg][tt][2] + bA + d1 * wA, 0.0f));
            Acol[r1 * PA + c + 1] = to_tf32(fmaxf(acc[mg][tt][3] + bB + d1 * wB, 0.0f));
        }
    }

    // ---- GEMM2: E2 = C1 @ eW2 ---- (first internal sync orders C1 writes)
    zero8(acc);
    gemm_pass(Acol, eW2, Wbuf, acc, tid, lane, m_base, n_base);

    // epilogue 2: +bias -> atomic scatter to g_m[row]; tf32 stash -> Arow
#pragma unroll
    for (int mg = 0; mg < 2; mg++) {
        const int r0 = m_base + mg * 16 + g, r1 = r0 + 8;
        float* m0 = g_m + (size_t)srow[r0] * HH;
        float* m1 = g_m + (size_t)srow[r1] * HH;
#pragma unroll
        for (int tt = 0; tt < 8; tt++) {
            int c = n_base + tt * 8 + t * 2;
            float bA = sm[S_EB2 + c], bB = sm[S_EB2 + c + 1];
            float v00 = acc[mg][tt][0] + bA, v01 = acc[mg][tt][1] + bB;
            float v10 = acc[mg][tt][2] + bA, v11 = acc[mg][tt][3] + bB;
            atomicAdd(&m0[c], v00);  atomicAdd(&m0[c + 1], v01);
            atomicAdd(&m1[c], v10);  atomicAdd(&m1[c + 1], v11);
            Arow[r0 * PA + c]     = to_tf32(v00);
            Arow[r0 * PA + c + 1] = to_tf32(v01);
            Arow[r1 * PA + c]     = to_tf32(v10);
            Arow[r1 * PA + c + 1] = to_tf32(v11);
        }
    }

    // ---- GEMM3: C3 = relu(E2 @ cW1 + cb1); alpha = C3 @ cW2 + cb2 ----
    zero8(acc);
    gemm_pass(Arow, cW1, Wbuf, acc, tid, lane, m_base, n_base);
#pragma unroll
    for (int mg = 0; mg < 2; mg++) {
        float p0 = 0.0f, p1 = 0.0f;
#pragma unroll
        for (int tt = 0; tt < 8; tt++) {
            int c = n_base + tt * 8 + t * 2;
            float bA = sm[S_CB1 + c], bB = sm[S_CB1 + c + 1];
            float wA = sm[S_CW2 + c], wB = sm[S_CW2 + c + 1];
            p0 = fmaf(fmaxf(acc[mg][tt][0] + bA, 0.0f), wA, p0);
            p0 = fmaf(fmaxf(acc[mg][tt][1] + bB, 0.0f), wB, p0);
            p1 = fmaf(fmaxf(acc[mg][tt][2] + bA, 0.0f), wA, p1);
            p1 = fmaf(fmaxf(acc[mg][tt][3] + bB, 0.0f), wB, p1);
        }
        p0 += __shfl_xor_sync(0xffffffffu, p0, 1);
        p0 += __shfl_xor_sync(0xffffffffu, p0, 2);
        p1 += __shfl_xor_sync(0xffffffffu, p1, 1);
        p1 += __shfl_xor_sync(0xffffffffu, p1, 2);
        if (t == 0) {
            spart[(m_base + mg * 16 + g) * 2 + wn]     = p0;
            spart[(m_base + mg * 16 + g + 8) * 2 + wn] = p1;
        }
    }
    __syncthreads();

    if (tid < TE) {
        float alpha = spart[tid * 2] + spart[tid * 2 + 1] + cb2[0];
        int node = srow[tid];
        atomicAdd(&g_xacc[node * 3 + 0], alpha * srel[tid * 3 + 0]);
        atomicAdd(&g_xacc[node * 3 + 1], alpha * srel[tid * 3 + 1]);
        atomicAdd(&g_xacc[node * 3 + 2], alpha * srel[tid * 3 + 2]);
    }
}

// ===========================================================================
// Scalar node-side machinery (3% of FLOPs)
// ===========================================================================
__device__ __forceinline__ void mm_tile(const float* __restrict__ As, int lda,
                                        const float* __restrict__ Wg,
                                        float* Ws, int K, int tid, int rg, int cg,
                                        float acc[4][8])
{
    const int r0 = rg * 4;
    const int c0 = cg * 8;
    for (int k0 = 0; k0 < K; k0 += 8) {
        __syncthreads();
        for (int j = tid; j < 8 * 128; j += NT)
            Ws[j] = Wg[k0 * 128 + j];
        __syncthreads();
#pragma unroll
        for (int q = 0; q < 2; q++) {
            float4 a4[4];
#pragma unroll
            for (int i = 0; i < 4; i++)
                a4[i] = *(const float4*)&As[(r0 + i) * lda + k0 + q * 4];
#pragma unroll
            for (int tt = 0; tt < 4; tt++) {
                const float* wr = &Ws[(q * 4 + tt) * 128 + c0];
                float4 b0 = *(const float4*)wr;
                float4 b1 = *(const float4*)(wr + 4);
                float bv[8] = {b0.x, b0.y, b0.z, b0.w, b1.x, b1.y, b1.z, b1.w};
                float av[4];
                av[0] = ((const float*)&a4[0])[tt];
                av[1] = ((const float*)&a4[1])[tt];
                av[2] = ((const float*)&a4[2])[tt];
                av[3] = ((const float*)&a4[3])[tt];
#pragma unroll
                for (int i = 0; i < 4; i++)
#pragma unroll
                    for (int jj = 0; jj < 8; jj++)
                        acc[i][jj] = fmaf(av[i], bv[jj], acc[i][jj]);
            }
        }
    }
}

__device__ __forceinline__ void zero_acc(float acc[4][8]) {
#pragma unroll
    for (int i = 0; i < 4; i++)
#pragma unroll
        for (int j = 0; j < 8; j++) acc[i][j] = 0.0f;
}

__global__ void __launch_bounds__(NT, 2) node_kernel(
    const float* __restrict__ nW1, const float* __restrict__ nb1,
    const float* __restrict__ nW2, const float* __restrict__ nb2,
    float* __restrict__ out_h, float* __restrict__ out_x)
{
    extern __shared__ float sm[];
    float* feat = sm;                   // 64*256
    float* bufB = sm + TN * FPN;        // 64*132
    float* Ws   = bufB + TN * FP2;      // 8*128

    const int tid = threadIdx.x;
    const int n0 = blockIdx.x * TN;

    for (int j = tid; j < TN * 32; j += NT) {
        int e = j >> 5, c4 = j & 31;
        int n = n0 + e; if (n >= NN) n = NN - 1;
        *(float4*)&feat[e * FPN + c4 * 4]       = ((const float4*)(g_h + (size_t)n * HH))[c4];
        *(float4*)&feat[e * FPN + 128 + c4 * 4] = ((const float4*)(g_m + (size_t)n * HH))[c4];
    }

    const int rg = tid >> 4, cg = tid & 15;
    const int r0 = rg * 4, c0 = cg * 8;
    float acc[4][8];

    zero_acc(acc);
    mm_tile(feat, FPN, nW1, Ws, 2 * HH, tid, rg, cg, acc);
    {
        float b1v[8];
#pragma unroll
        for (int jj = 0; jj < 8; jj++) b1v[jj] = nb1[c0 + jj];
#pragma unroll
        for (int i = 0; i < 4; i++)
#pragma unroll
            for (int jj = 0; jj < 8; jj++) {
                float v = acc[i][jj] + b1v[jj];
                bufB[(r0 + i) * FP2 + c0 + jj] = fmaxf(v, 0.0f);
            }
    }

    zero_acc(acc);
    mm_tile(bufB, FP2, nW2, Ws, HH, tid, rg, cg, acc);
    {
        float b2v[8];
#pragma unroll
        for (int jj = 0; jj < 8; jj++) b2v[jj] = nb2[c0 + jj];
#pragma unroll
        for (int i = 0; i < 4; i++) {
            int n = n0 + r0 + i;
            if (n < NN) {
#pragma unroll
                for (int jj = 0; jj < 8; jj++) {
                    float hv = feat[(r0 + i) * FPN + c0 + jj] + acc[i][jj] + b2v[jj];
                    g_h[(size_t)n * HH + c0 + jj] = hv;
                    if (out_h) out_h[(size_t)n * HH + c0 + jj] = hv;
                }
            }
        }
    }

    for (int t = tid; t < TN * 3; t += NT) {
        int n = n0 + t / 3;
        if (n < NN) {
            int d = t % 3;
            float xv = g_x[n * 3 + d] + g_xacc[n * 3 + d];
            g_x[n * 3 + d] = xv;
            if (out_x) out_x[n * 3 + d] = xv;
        }
    }
}

__global__ void embed_kernel(const float* __restrict__ hin,
                             const float* __restrict__ W,
                             const float* __restrict__ b)
{
    int j = blockIdx.x * blockDim.x + threadIdx.x;
    if (j >= NN * HH) return;
    int n = j >> 7, c = j & 127;
    float acc = b[c];
#pragma unroll
    for (int k = 0; k < 16; k++)
        acc = fmaf(hin[n * 16 + k], W[k * 128 + c], acc);
    g_h[j] = acc;
}

__global__ void xcopy_kernel(const float* __restrict__ xin)
{
    int i = blockIdx.x * blockDim.x + threadIdx.x;
    if (i < NN * 3) g_x[i] = xin[i];
}

__global__ void zero_kernel()
{
    int i = blockIdx.x * blockDim.x + threadIdx.x;
    if (i < NN * HH) g_m[i] = 0.0f;
    if (i < NN * 3) g_xacc[i] = 0.0f;
}

extern "C" void kernel_launch(void* const* d_in, const int* in_sizes, int n_in,
                              void* d_out, int out_size)
{
    const float* h_in  = (const float*)d_in[0];
    const float* x_in  = (const float*)d_in[1];
    const int*   ei    = (const int*)d_in[2];
    const float* emb_W = (const float*)d_in[3];
    const float* emb_b = (const float*)d_in[4];
    const float* eW1   = (const float*)d_in[5];
    const float* eb1   = (const float*)d_in[6];
    const float* eW2   = (const float*)d_in[7];
    const float* eb2   = (const float*)d_in[8];
    const float* nW1   = (const float*)d_in[9];
    const float* nb1   = (const float*)d_in[10];
    const float* nW2   = (const float*)d_in[11];
    const float* nb2   = (const float*)d_in[12];
    const float* cW1   = (const float*)d_in[13];
    const float* cb1   = (const float*)d_in[14];
    const float* cW2   = (const float*)d_in[15];
    const float* cb2   = (const float*)d_in[16];
    float* out = (float*)d_out;

    const int NODE_SMEM = (TN * FPN + TN * FP2 + 8 * 128) * 4;

    cudaFuncSetAttribute(edge_kernel, cudaFuncAttributeMaxDynamicSharedMemorySize, EDGE_SMEM_BYTES);
    cudaFuncSetAttribute(node_kernel, cudaFuncAttributeMaxDynamicSharedMemorySize, NODE_SMEM);

    xcopy_kernel<<<(NN * 3 + 255) / 256, 256>>>(x_in);
    embed_kernel<<<(NN * HH + 255) / 256, 256>>>(h_in, emb_W, emb_b);

    for (int l = 0; l < 2; l++) {
        zero_kernel<<<(NN * HH + 255) / 256, 256>>>();
        edge_kernel<<<EE / TE, NT, EDGE_SMEM_BYTES>>>(ei, eW1, eb1, eW2, eb2, cW1, cb1, cW2, cb2);
        bool fin = (l == 1);
        node_kernel<<<(NN + TN - 1) / TN, NT, NODE_SMEM>>>(
            nW1, nb1, nW2, nb2,
            fin ? out : (float*)nullptr,
            fin ? out + (size_t)NN * HH : (float*)nullptr);
    }
}

// round 6
// speedup vs baseline: 5.0818x; 1.2297x over previous
#include <cuda_runtime.h>
#include <cstdint>

#define NN 20000
#define EE 640000
#define HH 128
#define TE 64           // edges per block (edge kernel)
#define NT 256
#define TN 64           // nodes per block (node kernel)

// Scratch state (device globals: no allocation allowed)
__device__ float g_h[NN * HH];
__device__ float g_x[NN * 3];
__device__ float g_m[NN * HH];
__device__ float g_xacc[NN * 3];
// tf32-pre-rounded weights, [k][n] row-major 128x128 each:
// 0=eW1[0:128] 1=eW1[128:256] 2=eW2 3=cW1 4=nW1[0:128] 5=nW1[128:256] 6=nW2
__device__ uint32_t g_wp[7 * 128 * 128];

// ===========================================================================
// tf32 helpers
// ===========================================================================
__device__ __forceinline__ uint32_t to_tf32u(float x) {
    uint32_t r;
    asm("cvt.rna.tf32.f32 %0, %1;" : "=r"(r) : "f"(x));
    return r;
}
__device__ __forceinline__ float to_tf32(float x) { return __uint_as_float(to_tf32u(x)); }

__device__ __forceinline__ void mma8(float* c,
                                     uint32_t a0, uint32_t a1, uint32_t a2, uint32_t a3,
                                     uint32_t b0, uint32_t b1) {
    asm volatile(
        "mma.sync.aligned.m16n8k8.row.col.f32.tf32.tf32.f32 "
        "{%0,%1,%2,%3}, {%4,%5,%6,%7}, {%8,%9}, {%0,%1,%2,%3};"
        : "+f"(c[0]), "+f"(c[1]), "+f"(c[2]), "+f"(c[3])
        : "r"(a0), "r"(a1), "r"(a2), "r"(a3), "r"(b0), "r"(b1));
}

// ===========================================================================
// smem layouts (float indices)
// ===========================================================================
#define PA 132            // A-tile pitch: (4g+t)%32 distinct -> conflict-free
#define PW 136            // W-chunk pitch: (8t+g)%32 distinct -> conflict-free
// edge kernel
#define S_AROW 0                          // 64*132
#define S_ACOL (S_AROW + TE * PA)         // 64*132
#define S_WBUF (S_ACOL + TE * PA)         // 2*32*136
#define S_EB1  (S_WBUF + 2 * 32 * PW)
#define S_EB2  (S_EB1 + 128)
#define S_CB1  (S_EB2 + 128)
#define S_CW2  (S_CB1 + 128)
#define S_W1L  (S_CW2 + 128)
#define S_SROW (S_W1L + 128)              // int[64]
#define S_SCOL (S_SROW + TE)              // int[64]
#define S_SREL (S_SCOL + TE)              // 64*3
#define S_SRD  (S_SREL + TE * 3)          // 64
#define S_PART (S_SRD + TE)               // 64*4
#define S_TOT  (S_PART + TE * 4)
#define EDGE_SMEM_BYTES (S_TOT * 4)
// node kernel
#define N_AH   0                          // 64*132
#define N_AM   (N_AH + TN * PA)           // 64*132
#define N_WBUF (N_AM + TN * PA)           // 2*32*136
#define N_B1   (N_WBUF + 2 * 32 * PW)
#define N_B2   (N_B1 + 128)
#define N_TOT  (N_B2 + 128)
#define NODE_SMEM_BYTES (N_TOT * 4)

// ---------------------------------------------------------------------------
// GEMM pass: acc[2][4][4] += As[64,128] @ Wg[128,128]^T-frag (warp 32x32 slice)
// As: smem tf32, pitch PA. Wg: global tf32 [k][n]. Double-buffered K=32 chunks.
// Warp tile: 32 rows (m_base; 2 m16) x 32 cols (n_base; 4 n8).
// ---------------------------------------------------------------------------
__device__ __forceinline__ void gemm_pass(const float* __restrict__ As,
                                          const uint32_t* __restrict__ Wg,
                                          float* __restrict__ Wbuf,
                                          float acc[2][4][4],
                                          int tid, int lane, int m_base, int n_base)
{
    const int g = lane >> 2, t = lane & 3;

    uint4 pre[4];
#pragma unroll
    for (int q = 0; q < 4; q++) pre[q] = ((const uint4*)Wg)[tid + 256 * q];
#pragma unroll
    for (int q = 0; q < 4; q++) {
        int j = tid + 256 * q;
        *(uint4*)&Wbuf[(j >> 5) * PW + (j & 31) * 4] = pre[q];
    }
    __syncthreads();

    for (int ch = 0; ch < 4; ch++) {
        const int cur = ch & 1;
        if (ch < 3) {
#pragma unroll
            for (int q = 0; q < 4; q++)
                pre[q] = ((const uint4*)(Wg + (ch + 1) * 4096))[tid + 256 * q];
        }
        const uint32_t* Wc = (const uint32_t*)(Wbuf + cur * (32 * PW));
#pragma unroll
        for (int ks = 0; ks < 4; ks++) {
            const int krow = ch * 32 + ks * 8;
            const uint32_t* A0 = (const uint32_t*)As + (m_base + g) * PA + krow + t;
            uint32_t a00 = A0[0], a01 = A0[8 * PA], a02 = A0[4], a03 = A0[8 * PA + 4];
            const uint32_t* A1 = A0 + 16 * PA;
            uint32_t a10 = A1[0], a11 = A1[8 * PA], a12 = A1[4], a13 = A1[8 * PA + 4];
            const uint32_t* Bb = Wc + (ks * 8 + t) * PW + n_base + g;
#pragma unroll
            for (int nt = 0; nt < 4; nt++) {
                uint32_t b0 = Bb[nt * 8];
                uint32_t b1 = Bb[4 * PW + nt * 8];
                mma8(acc[0][nt], a00, a01, a02, a03, b0, b1);
                mma8(acc[1][nt], a10, a11, a12, a13, b0, b1);
            }
        }
        if (ch < 3) {
            float* dst = Wbuf + (cur ^ 1) * (32 * PW);
#pragma unroll
            for (int q = 0; q < 4; q++) {
                int j = tid + 256 * q;
                *(uint4*)&dst[(j >> 5) * PW + (j & 31) * 4] = pre[q];
            }
        }
        __syncthreads();
    }
}

__device__ __forceinline__ void zacc(float acc[2][4][4]) {
#pragma unroll
    for (int m = 0; m < 2; m++)
#pragma unroll
        for (int n = 0; n < 4; n++)
#pragma unroll
            for (int j = 0; j < 4; j++) acc[m][n][j] = 0.0f;
}

// prep: tf32-convert all 7 weight tiles into g_wp ([k][n] layout)
__global__ void prep_kernel(const float* __restrict__ eW1,
                            const float* __restrict__ eW2,
                            const float* __restrict__ cW1,
                            const float* __restrict__ nW1,
                            const float* __restrict__ nW2)
{
    int idx = blockIdx.x * blockDim.x + threadIdx.x;
    if (idx >= 7 * 16384) return;
    int mat = idx >> 14;
    int j   = idx & 16383;              // k*128 + n
    float v;
    switch (mat) {
        case 0: v = eW1[j]; break;
        case 1: v = eW1[128 * 128 + j]; break;
        case 2: v = eW2[j]; break;
        case 3: v = cW1[j]; break;
        case 4: v = nW1[j]; break;
        case 5: v = nW1[128 * 128 + j]; break;
        default: v = nW2[j]; break;
    }
    g_wp[idx] = to_tf32u(v);
}

// ---------------------------------------------------------------------------
// Fused edge pass. 64-edge tile, 8 warps (2 M-groups x 4 N-groups), 2 CTA/SM.
// ---------------------------------------------------------------------------
__global__ void __launch_bounds__(NT, 2) edge_kernel(
    const int* __restrict__ ei,
    const float* __restrict__ eb1, const float* __restrict__ eb2,
    const float* __restrict__ cb1, const float* __restrict__ cW2,
    const float* __restrict__ cb2, const float* __restrict__ eW1)
{
    extern __shared__ float sm[];
    float* Arow = sm + S_AROW;
    float* Acol = sm + S_ACOL;          // becomes C1
    float* Wbuf = sm + S_WBUF;
    int*   srow = (int*)(sm + S_SROW);
    int*   scol = (int*)(sm + S_SCOL);
    float* srel = sm + S_SREL;
    float* srd  = sm + S_SRD;
    float* spart= sm + S_PART;

    const int tid  = threadIdx.x;
    const int lane = tid & 31;
    const int wid  = tid >> 5;
    const int m_base = (wid & 1) * 32;
    const int n_base = (wid >> 1) * 32;
    const int wn = wid >> 1;
    const int g = lane >> 2, t = lane & 3;
    const int e0 = blockIdx.x * TE;

    if (tid < TE) {
        int e = e0 + tid;
        int r = ei[e];
        int c = ei[EE + e];
        if ((unsigned)r >= NN) r = 0;
        if ((unsigned)c >= NN) c = 0;
        srow[tid] = r;
        scol[tid] = c;
        float dx = g_x[r * 3 + 0] - g_x[c * 3 + 0];
        float dy = g_x[r * 3 + 1] - g_x[c * 3 + 1];
        float dz = g_x[r * 3 + 2] - g_x[c * 3 + 2];
        srel[tid * 3 + 0] = dx; srel[tid * 3 + 1] = dy; srel[tid * 3 + 2] = dz;
        srd[tid] = dx * dx + dy * dy + dz * dz;
    }
    if (tid < 128) {
        sm[S_EB1 + tid] = eb1[tid];
        sm[S_EB2 + tid] = eb2[tid];
        sm[S_CB1 + tid] = cb1[tid];
        sm[S_CW2 + tid] = cW2[tid];
        sm[S_W1L + tid] = eW1[256 * 128 + tid];
    }
    __syncthreads();

    // gather h[row], h[col] -> tf32 tiles (L2-resident)
    for (int j = tid; j < TE * 32; j += NT) {
        int e = j >> 5, c4 = j & 31;
        float4 hr = ((const float4*)(g_h + (size_t)srow[e] * HH))[c4];
        float4 hc = ((const float4*)(g_h + (size_t)scol[e] * HH))[c4];
        *(float4*)&Arow[e * PA + c4 * 4] =
            make_float4(to_tf32(hr.x), to_tf32(hr.y), to_tf32(hr.z), to_tf32(hr.w));
        *(float4*)&Acol[e * PA + c4 * 4] =
            make_float4(to_tf32(hc.x), to_tf32(hc.y), to_tf32(hc.z), to_tf32(hc.w));
    }
    // (gemm_pass's first __syncthreads covers the gather)

    float acc[2][4][4];

    // ---- GEMM1: h_row @ W1a + h_col @ W1b ----
    zacc(acc);
    gemm_pass(Arow, g_wp,         Wbuf, acc, tid, lane, m_base, n_base);
    gemm_pass(Acol, g_wp + 16384, Wbuf, acc, tid, lane, m_base, n_base);

    // epilogue 1: + rd*w1_last + bias, relu, tf32 -> C1 (Acol reuse)
#pragma unroll
    for (int m = 0; m < 2; m++) {
        const int r0 = m_base + m * 16 + g, r1 = r0 + 8;
        float d0 = srd[r0], d1 = srd[r1];
#pragma unroll
        for (int nt = 0; nt < 4; nt++) {
            int c = n_base + nt * 8 + t * 2;
            float bA = sm[S_EB1 + c], bB = sm[S_EB1 + c + 1];
            float wA = sm[S_W1L + c], wB = sm[S_W1L + c + 1];
            Acol[r0 * PA + c]     = to_tf32(fmaxf(acc[m][nt][0] + bA + d0 * wA, 0.0f));
            Acol[r0 * PA + c + 1] = to_tf32(fmaxf(acc[m][nt][1] + bB + d0 * wB, 0.0f));
            Acol[r1 * PA + c]     = to_tf32(fmaxf(acc[m][nt][2] + bA + d1 * wA, 0.0f));
            Acol[r1 * PA + c + 1] = to_tf32(fmaxf(acc[m][nt][3] + bB + d1 * wB, 0.0f));
        }
    }

    // ---- GEMM2: E2 = C1 @ eW2 ---- (first internal sync orders C1 writes)
    zacc(acc);
    gemm_pass(Acol, g_wp + 2 * 16384, Wbuf, acc, tid, lane, m_base, n_base);

    // epilogue 2: +bias -> atomic g_m[row]; tf32 stash -> Arow
#pragma unroll
    for (int m = 0; m < 2; m++) {
        const int r0 = m_base + m * 16 + g, r1 = r0 + 8;
        float* m0 = g_m + (size_t)srow[r0] * HH;
        float* m1 = g_m + (size_t)srow[r1] * HH;
#pragma unroll
        for (int nt = 0; nt < 4; nt++) {
            int c = n_base + nt * 8 + t * 2;
            float bA = sm[S_EB2 + c], bB = sm[S_EB2 + c + 1];
            float v00 = acc[m][nt][0] + bA, v01 = acc[m][nt][1] + bB;
            float v10 = acc[m][nt][2] + bA, v11 = acc[m][nt][3] + bB;
            atomicAdd(&m0[c], v00);  atomicAdd(&m0[c + 1], v01);
            atomicAdd(&m1[c], v10);  atomicAdd(&m1[c + 1], v11);
            Arow[r0 * PA + c]     = to_tf32(v00);
            Arow[r0 * PA + c + 1] = to_tf32(v01);
            Arow[r1 * PA + c]     = to_tf32(v10);
            Arow[r1 * PA + c + 1] = to_tf32(v11);
        }
    }

    // ---- GEMM3: C3 = relu(E2 @ cW1 + cb1); alpha = C3 . cW2 + cb2 ----
    zacc(acc);
    gemm_pass(Arow, g_wp + 3 * 16384, Wbuf, acc, tid, lane, m_base, n_base);
#pragma unroll
    for (int m = 0; m < 2; m++) {
        const int r0 = m_base + m * 16 + g;
        float p0 = 0.0f, p1 = 0.0f;
#pragma unroll
        for (int nt = 0; nt < 4; nt++) {
            int c = n_base + nt * 8 + t * 2;
            float bA = sm[S_CB1 + c], bB = sm[S_CB1 + c + 1];
            float wA = sm[S_CW2 + c], wB = sm[S_CW2 + c + 1];
            p0 = fmaf(fmaxf(acc[m][nt][0] + bA, 0.0f), wA, p0);
            p0 = fmaf(fmaxf(acc[m][nt][1] + bB, 0.0f), wB, p0);
            p1 = fmaf(fmaxf(acc[m][nt][2] + bA, 0.0f), wA, p1);
            p1 = fmaf(fmaxf(acc[m][nt][3] + bB, 0.0f), wB, p1);
        }
        p0 += __shfl_xor_sync(0xffffffffu, p0, 1);
        p0 += __shfl_xor_sync(0xffffffffu, p0, 2);
        p1 += __shfl_xor_sync(0xffffffffu, p1, 1);
        p1 += __shfl_xor_sync(0xffffffffu, p1, 2);
        if (t == 0) {
            spart[r0 * 4 + wn]       = p0;
            spart[(r0 + 8) * 4 + wn] = p1;
        }
    }
    __syncthreads();

    if (tid < TE) {
        float alpha = spart[tid * 4] + spart[tid * 4 + 1] + spart[tid * 4 + 2]
                    + spart[tid * 4 + 3] + cb2[0];
        int node = srow[tid];
        atomicAdd(&g_xacc[node * 3 + 0], alpha * srel[tid * 3 + 0]);
        atomicAdd(&g_xacc[node * 3 + 1], alpha * srel[tid * 3 + 1]);
        atomicAdd(&g_xacc[node * 3 + 2], alpha * srel[tid * 3 + 2]);
    }
}

// ---------------------------------------------------------------------------
// Node update (tensorized): h += relu([h,m] @ nW1 + nb1) @ nW2 + nb2; x += xacc
// ---------------------------------------------------------------------------
__global__ void __launch_bounds__(NT, 2) node_kernel(
    const float* __restrict__ nb1, const float* __restrict__ nb2,
    float* __restrict__ out_h, float* __restrict__ out_x)
{
    extern __shared__ float sm[];
    float* AH   = sm + N_AH;            // h tf32; reused as C1
    float* AM   = sm + N_AM;            // m tf32
    float* Wbuf = sm + N_WBUF;

    const int tid  = threadIdx.x;
    const int lane = tid & 31;
    const int wid  = tid >> 5;
    const int m_base = (wid & 1) * 32;
    const int n_base = (wid >> 1) * 32;
    const int g = lane >> 2, t = lane & 3;
    const int n0 = blockIdx.x * TN;

    if (tid < 128) {
        sm[N_B1 + tid] = nb1[tid];
        sm[N_B2 + tid] = nb2[tid];
    }

    for (int j = tid; j < TN * 32; j += NT) {
        int e = j >> 5, c4 = j & 31;
        int n = n0 + e; if (n >= NN) n = NN - 1;
        float4 hv = ((const float4*)(g_h + (size_t)n * HH))[c4];
        float4 mv = ((const float4*)(g_m + (size_t)n * HH))[c4];
        *(float4*)&AH[e * PA + c4 * 4] =
            make_float4(to_tf32(hv.x), to_tf32(hv.y), to_tf32(hv.z), to_tf32(hv.w));
        *(float4*)&AM[e * PA + c4 * 4] =
            make_float4(to_tf32(mv.x), to_tf32(mv.y), to_tf32(mv.z), to_tf32(mv.w));
    }

    float acc[2][4][4];

    // GEMM1: [h|m] @ nW1 (K=256 as two accumulating K=128 passes)
    zacc(acc);
    gemm_pass(AH, g_wp + 4 * 16384, Wbuf, acc, tid, lane, m_base, n_base);
    gemm_pass(AM, g_wp + 5 * 16384, Wbuf, acc, tid, lane, m_base, n_base);

    // epilogue 1: relu(+nb1) -> tf32 into AH (reused as C1)
#pragma unroll
    for (int m = 0; m < 2; m++) {
        const int r0 = m_base + m * 16 + g, r1 = r0 + 8;
#pragma unroll
        for (int nt = 0; nt < 4; nt++) {
            int c = n_base + nt * 8 + t * 2;
            float bA = sm[N_B1 + c], bB = sm[N_B1 + c + 1];
            AH[r0 * PA + c]     = to_tf32(fmaxf(acc[m][nt][0] + bA, 0.0f));
            AH[r0 * PA + c + 1] = to_tf32(fmaxf(acc[m][nt][1] + bB, 0.0f));
            AH[r1 * PA + c]     = to_tf32(fmaxf(acc[m][nt][2] + bA, 0.0f));
            AH[r1 * PA + c + 1] = to_tf32(fmaxf(acc[m][nt][3] + bB, 0.0f));
        }
    }

    // GEMM2: C1 @ nW2
    zacc(acc);
    gemm_pass(AH, g_wp + 6 * 16384, Wbuf, acc, tid, lane, m_base, n_base);

    // epilogue 2: h_new = h_old + acc + nb2 -> g_h (+ out)
#pragma unroll
    for (int m = 0; m < 2; m++) {
#pragma unroll
        for (int half = 0; half < 2; half++) {
            const int r = m_base + m * 16 + g + half * 8;
            const int n = n0 + r;
            if (n < NN) {
#pragma unroll
                for (int nt = 0; nt < 4; nt++) {
                    int c = n_base + nt * 8 + t * 2;
                    float a0 = acc[m][nt][half * 2 + 0];
                    float a1 = acc[m][nt][half * 2 + 1];
                    float h0 = g_h[(size_t)n * HH + c]     + a0 + sm[N_B2 + c];
                    float h1 = g_h[(size_t)n * HH + c + 1] + a1 + sm[N_B2 + c + 1];
                    g_h[(size_t)n * HH + c]     = h0;
                    g_h[(size_t)n * HH + c + 1] = h1;
                    if (out_h) {
                        out_h[(size_t)n * HH + c]     = h0;
                        out_h[(size_t)n * HH + c + 1] = h1;
                    }
                }
            }
        }
    }

    for (int tt = tid; tt < TN * 3; tt += NT) {
        int n = n0 + tt / 3;
        if (n < NN) {
            int d = tt % 3;
            float xv = g_x[n * 3 + d] + g_xacc[n * 3 + d];
            g_x[n * 3 + d] = xv;
            if (out_x) out_x[n * 3 + d] = xv;
        }
    }
}

// ===========================================================================
// small setup kernels
// ===========================================================================
__global__ void embed_kernel(const float* __restrict__ hin,
                             const float* __restrict__ W,
                             const float* __restrict__ b)
{
    int j = blockIdx.x * blockDim.x + threadIdx.x;
    if (j >= NN * HH) return;
    int n = j >> 7, c = j & 127;
    float acc = b[c];
#pragma unroll
    for (int k = 0; k < 16; k++)
        acc = fmaf(hin[n * 16 + k], W[k * 128 + c], acc);
    g_h[j] = acc;
}

__global__ void xcopy_kernel(const float* __restrict__ xin)
{
    int i = blockIdx.x * blockDim.x + threadIdx.x;
    if (i < NN * 3) g_x[i] = xin[i];
}

__global__ void zero_kernel()
{
    int i = blockIdx.x * blockDim.x + threadIdx.x;
    if (i < NN * HH) g_m[i] = 0.0f;
    if (i < NN * 3) g_xacc[i] = 0.0f;
}

extern "C" void kernel_launch(void* const* d_in, const int* in_sizes, int n_in,
                              void* d_out, int out_size)
{
    const float* h_in  = (const float*)d_in[0];
    const float* x_in  = (const float*)d_in[1];
    const int*   ei    = (const int*)d_in[2];
    const float* emb_W = (const float*)d_in[3];
    const float* emb_b = (const float*)d_in[4];
    const float* eW1   = (const float*)d_in[5];
    const float* eb1   = (const float*)d_in[6];
    const float* eW2   = (const float*)d_in[7];
    const float* eb2   = (const float*)d_in[8];
    const float* nW1   = (const float*)d_in[9];
    const float* nb1   = (const float*)d_in[10];
    const float* nW2   = (const float*)d_in[11];
    const float* nb2   = (const float*)d_in[12];
    const float* cW1   = (const float*)d_in[13];
    const float* cb1   = (const float*)d_in[14];
    const float* cW2   = (const float*)d_in[15];
    const float* cb2   = (const float*)d_in[16];
    float* out = (float*)d_out;

    cudaFuncSetAttribute(edge_kernel, cudaFuncAttributeMaxDynamicSharedMemorySize, EDGE_SMEM_BYTES);
    cudaFuncSetAttribute(node_kernel, cudaFuncAttributeMaxDynamicSharedMemorySize, NODE_SMEM_BYTES);

    xcopy_kernel<<<(NN * 3 + 255) / 256, 256>>>(x_in);
    embed_kernel<<<(NN * HH + 255) / 256, 256>>>(h_in, emb_W, emb_b);
    prep_kernel<<<(7 * 16384 + 255) / 256, 256>>>(eW1, eW2, cW1, nW1, nW2);

    for (int l = 0; l < 2; l++) {
        zero_kernel<<<(NN * HH + 255) / 256, 256>>>();
        edge_kernel<<<EE / TE, NT, EDGE_SMEM_BYTES>>>(ei, eb1, eb2, cb1, cW2, cb2, eW1);
        bool fin = (l == 1);
        node_kernel<<<(NN + TN - 1) / TN, NT, NODE_SMEM_BYTES>>>(
            nb1, nb2,
            fin ? out : (float*)nullptr,
            fin ? out + (size_t)NN * HH : (float*)nullptr);
    }
}

// round 7
// speedup vs baseline: 8.2781x; 1.6290x over previous
#include <cuda_runtime.h>
#include <cuda_fp16.h>
#include <cstdint>

#define NN 20000
#define EE 640000
#define HH 128
#define TE 64           // edges per block (edge kernel)
#define NT 256
#define TN 64           // nodes per block (node kernel)

// Scratch state (device globals: no allocation allowed)
__device__ float g_h[NN * HH];
__device__ float g_x[NN * 3];
__device__ float g_m[NN * HH];
__device__ float g_xacc[NN * 3];
// fp16-packed transposed weights, chunk-major [4][128n][16kpair] uint32 each:
// 0=eW1[0:128] 1=eW1[128:256] 2=eW2 3=cW1 4=nW1[0:128] 5=nW1[128:256] 6=nW2
__device__ uint32_t g_wp[7 * 8192];

// ===========================================================================
// helpers
// ===========================================================================
__device__ __forceinline__ uint32_t pack_h2(float a, float b) {
    __half2 h = __floats2half2_rn(a, b);
    return *(uint32_t*)&h;
}

__device__ __forceinline__ void mma16h(float* c,
                                       uint32_t a0, uint32_t a1, uint32_t a2, uint32_t a3,
                                       uint32_t b0, uint32_t b1) {
    asm volatile(
        "mma.sync.aligned.m16n8k16.row.col.f32.f16.f16.f32 "
        "{%0,%1,%2,%3}, {%4,%5,%6,%7}, {%8,%9}, {%0,%1,%2,%3};"
        : "+f"(c[0]), "+f"(c[1]), "+f"(c[2]), "+f"(c[3])
        : "r"(a0), "r"(a1), "r"(a2), "r"(a3), "r"(b0), "r"(b1));
}

// ===========================================================================
// smem layouts (uint32 indices)
// ===========================================================================
#define PAH 68            // A pitch in uint32 kpairs: (4g+t)%32 distinct
#define PWH 20            // W pitch in uint32 kpairs: (20g+t)%32 distinct
// edge kernel
#define S_AROW 0                          // 64*68 = 4352
#define S_ACOL (S_AROW + TE * PAH)        // 4352
#define S_WBUF (S_ACOL + TE * PAH)        // 2*128*20 = 5120
#define S_EB1  (S_WBUF + 2 * 128 * PWH)   // 128 (floats)
#define S_EB2  (S_EB1 + 128)
#define S_CB1  (S_EB2 + 128)
#define S_CW2  (S_CB1 + 128)
#define S_W1L  (S_CW2 + 128)
#define S_SROW (S_W1L + 128)              // int[64]
#define S_SCOL (S_SROW + TE)
#define S_SREL (S_SCOL + TE)              // 64*3 floats
#define S_SRD  (S_SREL + TE * 3)          // 64
#define S_PART (S_SRD + TE)               // 64*4
#define S_TOT  (S_PART + TE * 4)
#define EDGE_SMEM_BYTES (S_TOT * 4)
// node kernel
#define N_AH   0
#define N_AM   (N_AH + TN * PAH)
#define N_WBUF (N_AM + TN * PAH)
#define N_B1   (N_WBUF + 2 * 128 * PWH)
#define N_B2   (N_B1 + 128)
#define N_TOT  (N_B2 + 128)
#define NODE_SMEM_BYTES (N_TOT * 4)

// ---------------------------------------------------------------------------
// fp16 GEMM pass: acc[2][4][4] += As[64,128] @ W[128,128] (warp 32x32 slice)
// As: smem packed half2 [row][kpair] pitch PAH. Wg: global chunk-major packed.
// Double-buffered K=32 chunks (16 kpairs). m16n8k16 MMAs.
// ---------------------------------------------------------------------------
__device__ __forceinline__ void gemm_pass_h(const uint32_t* __restrict__ As,
                                            const uint32_t* __restrict__ Wg,
                                            uint32_t* __restrict__ Wbuf,
                                            float acc[2][4][4],
                                            int tid, int lane, int m_base, int n_base)
{
    const int g = lane >> 2, t = lane & 3;

    uint4 pre0 = ((const uint4*)Wg)[tid];
    uint4 pre1 = ((const uint4*)Wg)[tid + 256];
    {
        *(uint4*)&Wbuf[(tid >> 2) * PWH + (tid & 3) * 4] = pre0;
        *(uint4*)&Wbuf[((tid + 256) >> 2) * PWH + (tid & 3) * 4] = pre1;
    }
    __syncthreads();

    for (int ch = 0; ch < 4; ch++) {
        const int cur = ch & 1;
        if (ch < 3) {
            pre0 = ((const uint4*)(Wg + (ch + 1) * 2048))[tid];
            pre1 = ((const uint4*)(Wg + (ch + 1) * 2048))[tid + 256];
        }
        const uint32_t* Wc = Wbuf + cur * (128 * PWH);
#pragma unroll
        for (int ks = 0; ks < 2; ks++) {
            const int kp = ch * 16 + ks * 8;      // kpair base in A
            const uint32_t* A0 = As + (m_base + g) * PAH + kp + t;
            uint32_t a00 = A0[0], a01 = A0[8 * PAH], a02 = A0[4], a03 = A0[8 * PAH + 4];
            const uint32_t* A1 = A0 + 16 * PAH;
            uint32_t a10 = A1[0], a11 = A1[8 * PAH], a12 = A1[4], a13 = A1[8 * PAH + 4];
            const int kb = ks * 8;                // kpair base within chunk
#pragma unroll
            for (int nt = 0; nt < 4; nt++) {
                const uint32_t* Bb = Wc + (n_base + nt * 8 + g) * PWH + kb + t;
                uint32_t b0 = Bb[0];
                uint32_t b1 = Bb[4];
                mma16h(acc[0][nt], a00, a01, a02, a03, b0, b1);
                mma16h(acc[1][nt], a10, a11, a12, a13, b0, b1);
            }
        }
        if (ch < 3) {
            uint32_t* dst = Wbuf + (cur ^ 1) * (128 * PWH);
            *(uint4*)&dst[(tid >> 2) * PWH + (tid & 3) * 4] = pre0;
            *(uint4*)&dst[((tid + 256) >> 2) * PWH + (tid & 3) * 4] = pre1;
        }
        __syncthreads();
    }
}

__device__ __forceinline__ void zacc(float acc[2][4][4]) {
#pragma unroll
    for (int m = 0; m < 2; m++)
#pragma unroll
        for (int n = 0; n < 4; n++)
#pragma unroll
            for (int j = 0; j < 4; j++) acc[m][n][j] = 0.0f;
}

// prep: fp16-pack all 7 weight tiles, transposed [n][k], chunk-major
__global__ void prep_kernel(const float* __restrict__ eW1,
                            const float* __restrict__ eW2,
                            const float* __restrict__ cW1,
                            const float* __restrict__ nW1,
                            const float* __restrict__ nW2)
{
    int idx = blockIdx.x * blockDim.x + threadIdx.x;
    if (idx >= 7 * 8192) return;
    int mat = idx >> 13;
    int rem = idx & 8191;
    int chunk = rem >> 11;
    int n = (rem >> 4) & 127;
    int kp = rem & 15;
    int k = chunk * 32 + kp * 2;
    const float* W;
    int off = 0;
    switch (mat) {
        case 0: W = eW1; break;
        case 1: W = eW1; off = 128 * 128; break;
        case 2: W = eW2; break;
        case 3: W = cW1; break;
        case 4: W = nW1; break;
        case 5: W = nW1; off = 128 * 128; break;
        default: W = nW2; break;
    }
    g_wp[idx] = pack_h2(W[off + k * 128 + n], W[off + (k + 1) * 128 + n]);
}

// ---------------------------------------------------------------------------
// Fused edge pass. 64-edge tile, 8 warps (2 M x 4 N groups), 3 CTA/SM.
// ---------------------------------------------------------------------------
__global__ void __launch_bounds__(NT, 3) edge_kernel(
    const int* __restrict__ ei,
    const float* __restrict__ eb1, const float* __restrict__ eb2,
    const float* __restrict__ cb1, const float* __restrict__ cW2,
    const float* __restrict__ cb2, const float* __restrict__ eW1)
{
    extern __shared__ uint32_t smu[];
    float* smf = (float*)smu;
    uint32_t* Arow = smu + S_AROW;
    uint32_t* Acol = smu + S_ACOL;      // becomes C1
    uint32_t* Wbuf = smu + S_WBUF;
    int*   srow = (int*)(smu + S_SROW);
    int*   scol = (int*)(smu + S_SCOL);
    float* srel = smf + S_SREL;
    float* srd  = smf + S_SRD;
    float* spart= smf + S_PART;

    const int tid  = threadIdx.x;
    const int lane = tid & 31;
    const int wid  = tid >> 5;
    const int m_base = (wid & 1) * 32;
    const int n_base = (wid >> 1) * 32;
    const int wn = wid >> 1;
    const int g = lane >> 2, t = lane & 3;
    const int e0 = blockIdx.x * TE;

    if (tid < TE) {
        int e = e0 + tid;
        int r = ei[e];
        int c = ei[EE + e];
        if ((unsigned)r >= NN) r = 0;
        if ((unsigned)c >= NN) c = 0;
        srow[tid] = r;
        scol[tid] = c;
        float dx = g_x[r * 3 + 0] - g_x[c * 3 + 0];
        float dy = g_x[r * 3 + 1] - g_x[c * 3 + 1];
        float dz = g_x[r * 3 + 2] - g_x[c * 3 + 2];
        srel[tid * 3 + 0] = dx; srel[tid * 3 + 1] = dy; srel[tid * 3 + 2] = dz;
        srd[tid] = dx * dx + dy * dy + dz * dz;
    }
    if (tid < 128) {
        smf[S_EB1 + tid] = eb1[tid];
        smf[S_EB2 + tid] = eb2[tid];
        smf[S_CB1 + tid] = cb1[tid];
        smf[S_CW2 + tid] = cW2[tid];
        smf[S_W1L + tid] = eW1[256 * 128 + tid];
    }
    __syncthreads();

    // gather h[row], h[col] -> fp16-packed tiles (L2-resident)
    for (int j = tid; j < TE * 32; j += NT) {
        int e = j >> 5, c4 = j & 31;
        float4 hr = ((const float4*)(g_h + (size_t)srow[e] * HH))[c4];
        float4 hc = ((const float4*)(g_h + (size_t)scol[e] * HH))[c4];
        *(uint2*)&Arow[e * PAH + c4 * 2] =
            make_uint2(pack_h2(hr.x, hr.y), pack_h2(hr.z, hr.w));
        *(uint2*)&Acol[e * PAH + c4 * 2] =
            make_uint2(pack_h2(hc.x, hc.y), pack_h2(hc.z, hc.w));
    }
    // (gemm_pass_h's first __syncthreads covers the gather)

    float acc[2][4][4];

    // ---- GEMM1: h_row @ W1a + h_col @ W1b ----
    zacc(acc);
    gemm_pass_h(Arow, g_wp,        Wbuf, acc, tid, lane, m_base, n_base);
    gemm_pass_h(Acol, g_wp + 8192, Wbuf, acc, tid, lane, m_base, n_base);

    // epilogue 1: + rd*w1_last + bias, relu -> fp16 C1 (Acol reuse)
#pragma unroll
    for (int m = 0; m < 2; m++) {
        const int r0 = m_base + m * 16 + g, r1 = r0 + 8;
        float d0 = srd[r0], d1 = srd[r1];
#pragma unroll
        for (int nt = 0; nt < 4; nt++) {
            int c = n_base + nt * 8 + t * 2;
            float bA = smf[S_EB1 + c], bB = smf[S_EB1 + c + 1];
            float wA = smf[S_W1L + c], wB = smf[S_W1L + c + 1];
            Acol[r0 * PAH + (c >> 1)] = pack_h2(fmaxf(acc[m][nt][0] + bA + d0 * wA, 0.0f),
                                                fmaxf(acc[m][nt][1] + bB + d0 * wB, 0.0f));
            Acol[r1 * PAH + (c >> 1)] = pack_h2(fmaxf(acc[m][nt][2] + bA + d1 * wA, 0.0f),
                                                fmaxf(acc[m][nt][3] + bB + d1 * wB, 0.0f));
        }
    }

    // ---- GEMM2: E2 = C1 @ eW2 ---- (first internal sync orders C1 writes)
    zacc(acc);
    gemm_pass_h(Acol, g_wp + 2 * 8192, Wbuf, acc, tid, lane, m_base, n_base);

    // epilogue 2: +bias -> atomic g_m[row]; fp16 stash -> Arow
#pragma unroll
    for (int m = 0; m < 2; m++) {
        const int r0 = m_base + m * 16 + g, r1 = r0 + 8;
        float* m0 = g_m + (size_t)srow[r0] * HH;
        float* m1 = g_m + (size_t)srow[r1] * HH;
#pragma unroll
        for (int nt = 0; nt < 4; nt++) {
            int c = n_base + nt * 8 + t * 2;
            float bA = smf[S_EB2 + c], bB = smf[S_EB2 + c + 1];
            float v00 = acc[m][nt][0] + bA, v01 = acc[m][nt][1] + bB;
            float v10 = acc[m][nt][2] + bA, v11 = acc[m][nt][3] + bB;
            atomicAdd(&m0[c], v00);  atomicAdd(&m0[c + 1], v01);
            atomicAdd(&m1[c], v10);  atomicAdd(&m1[c + 1], v11);
            Arow[r0 * PAH + (c >> 1)] = pack_h2(v00, v01);
            Arow[r1 * PAH + (c >> 1)] = pack_h2(v10, v11);
        }
    }

    // ---- GEMM3: C3 = relu(E2 @ cW1 + cb1); alpha = C3 . cW2 + cb2 ----
    zacc(acc);
    gemm_pass_h(Arow, g_wp + 3 * 8192, Wbuf, acc, tid, lane, m_base, n_base);
#pragma unroll
    for (int m = 0; m < 2; m++) {
        const int r0 = m_base + m * 16 + g;
        float p0 = 0.0f, p1 = 0.0f;
#pragma unroll
        for (int nt = 0; nt < 4; nt++) {
            int c = n_base + nt * 8 + t * 2;
            float bA = smf[S_CB1 + c], bB = smf[S_CB1 + c + 1];
            float wA = smf[S_CW2 + c], wB = smf[S_CW2 + c + 1];
            p0 = fmaf(fmaxf(acc[m][nt][0] + bA, 0.0f), wA, p0);
            p0 = fmaf(fmaxf(acc[m][nt][1] + bB, 0.0f), wB, p0);
            p1 = fmaf(fmaxf(acc[m][nt][2] + bA, 0.0f), wA, p1);
            p1 = fmaf(fmaxf(acc[m][nt][3] + bB, 0.0f), wB, p1);
        }
        p0 += __shfl_xor_sync(0xffffffffu, p0, 1);
        p0 += __shfl_xor_sync(0xffffffffu, p0, 2);
        p1 += __shfl_xor_sync(0xffffffffu, p1, 1);
        p1 += __shfl_xor_sync(0xffffffffu, p1, 2);
        if (t == 0) {
            spart[r0 * 4 + wn]       = p0;
            spart[(r0 + 8) * 4 + wn] = p1;
        }
    }
    __syncthreads();

    if (tid < TE) {
        float alpha = spart[tid * 4] + spart[tid * 4 + 1] + spart[tid * 4 + 2]
                    + spart[tid * 4 + 3] + cb2[0];
        int node = srow[tid];
        atomicAdd(&g_xacc[node * 3 + 0], alpha * srel[tid * 3 + 0]);
        atomicAdd(&g_xacc[node * 3 + 1], alpha * srel[tid * 3 + 1]);
        atomicAdd(&g_xacc[node * 3 + 2], alpha * srel[tid * 3 + 2]);
    }
}

// ---------------------------------------------------------------------------
// Node update (fp16 tensor): h += relu([h,m] @ nW1 + nb1) @ nW2 + nb2; x += xacc
// ---------------------------------------------------------------------------
__global__ void __launch_bounds__(NT, 3) node_kernel(
    const float* __restrict__ nb1, const float* __restrict__ nb2,
    float* __restrict__ out_h, float* __restrict__ out_x)
{
    extern __shared__ uint32_t smu[];
    float* smf = (float*)smu;
    uint32_t* AH   = smu + N_AH;        // h fp16; reused as C1
    uint32_t* AM   = smu + N_AM;        // m fp16
    uint32_t* Wbuf = smu + N_WBUF;

    const int tid  = threadIdx.x;
    const int lane = tid & 31;
    const int wid  = tid >> 5;
    const int m_base = (wid & 1) * 32;
    const int n_base = (wid >> 1) * 32;
    const int g = lane >> 2, t = lane & 3;
    const int n0 = blockIdx.x * TN;

    if (tid < 128) {
        smf[N_B1 + tid] = nb1[tid];
        smf[N_B2 + tid] = nb2[tid];
    }

    for (int j = tid; j < TN * 32; j += NT) {
        int e = j >> 5, c4 = j & 31;
        int n = n0 + e; if (n >= NN) n = NN - 1;
        float4 hv = ((const float4*)(g_h + (size_t)n * HH))[c4];
        float4 mv = ((const float4*)(g_m + (size_t)n * HH))[c4];
        *(uint2*)&AH[e * PAH + c4 * 2] =
            make_uint2(pack_h2(hv.x, hv.y), pack_h2(hv.z, hv.w));
        *(uint2*)&AM[e * PAH + c4 * 2] =
            make_uint2(pack_h2(mv.x, mv.y), pack_h2(mv.z, mv.w));
    }

    float acc[2][4][4];

    // GEMM1: [h|m] @ nW1 (K=256 as two accumulating K=128 passes)
    zacc(acc);
    gemm_pass_h(AH, g_wp + 4 * 8192, Wbuf, acc, tid, lane, m_base, n_base);
    gemm_pass_h(AM, g_wp + 5 * 8192, Wbuf, acc, tid, lane, m_base, n_base);

    // epilogue 1: relu(+nb1) -> fp16 into AH (reused as C1)
#pragma unroll
    for (int m = 0; m < 2; m++) {
        const int r0 = m_base + m * 16 + g, r1 = r0 + 8;
#pragma unroll
        for (int nt = 0; nt < 4; nt++) {
            int c = n_base + nt * 8 + t * 2;
            float bA = smf[N_B1 + c], bB = smf[N_B1 + c + 1];
            AH[r0 * PAH + (c >> 1)] = pack_h2(fmaxf(acc[m][nt][0] + bA, 0.0f),
                                              fmaxf(acc[m][nt][1] + bB, 0.0f));
            AH[r1 * PAH + (c >> 1)] = pack_h2(fmaxf(acc[m][nt][2] + bA, 0.0f),
                                              fmaxf(acc[m][nt][3] + bB, 0.0f));
        }
    }

    // GEMM2: C1 @ nW2
    zacc(acc);
    gemm_pass_h(AH, g_wp + 6 * 8192, Wbuf, acc, tid, lane, m_base, n_base);

    // epilogue 2: h_new = h_old + acc + nb2 -> g_h (+ out)
#pragma unroll
    for (int m = 0; m < 2; m++) {
#pragma unroll
        for (int half = 0; half < 2; half++) {
            const int r = m_base + m * 16 + g + half * 8;
            const int n = n0 + r;
            if (n < NN) {
#pragma unroll
                for (int nt = 0; nt < 4; nt++) {
                    int c = n_base + nt * 8 + t * 2;
                    float a0 = acc[m][nt][half * 2 + 0];
                    float a1 = acc[m][nt][half * 2 + 1];
                    float h0 = g_h[(size_t)n * HH + c]     + a0 + smf[N_B2 + c];
                    float h1 = g_h[(size_t)n * HH + c + 1] + a1 + smf[N_B2 + c + 1];
                    g_h[(size_t)n * HH + c]     = h0;
                    g_h[(size_t)n * HH + c + 1] = h1;
                    if (out_h) {
                        out_h[(size_t)n * HH + c]     = h0;
                        out_h[(size_t)n * HH + c + 1] = h1;
                    }
                }
            }
        }
    }

    for (int tt = tid; tt < TN * 3; tt += NT) {
        int n = n0 + tt / 3;
        if (n < NN) {
            int d = tt % 3;
            float xv = g_x[n * 3 + d] + g_xacc[n * 3 + d];
            g_x[n * 3 + d] = xv;
            if (out_x) out_x[n * 3 + d] = xv;
        }
    }
}

// ===========================================================================
// small setup kernels
// ===========================================================================
__global__ void embed_kernel(const float* __restrict__ hin,
                             const float* __restrict__ W,
                             const float* __restrict__ b)
{
    int j = blockIdx.x * blockDim.x + threadIdx.x;
    if (j >= NN * HH) return;
    int n = j >> 7, c = j & 127;
    float acc = b[c];
#pragma unroll
    for (int k = 0; k < 16; k++)
        acc = fmaf(hin[n * 16 + k], W[k * 128 + c], acc);
    g_h[j] = acc;
}

__global__ void xcopy_kernel(const float* __restrict__ xin)
{
    int i = blockIdx.x * blockDim.x + threadIdx.x;
    if (i < NN * 3) g_x[i] = xin[i];
}

__global__ void zero_kernel()
{
    int i = blockIdx.x * blockDim.x + threadIdx.x;
    if (i < NN * HH) g_m[i] = 0.0f;
    if (i < NN * 3) g_xacc[i] = 0.0f;
}

extern "C" void kernel_launch(void* const* d_in, const int* in_sizes, int n_in,
                              void* d_out, int out_size)
{
    const float* h_in  = (const float*)d_in[0];
    const float* x_in  = (const float*)d_in[1];
    const int*   ei    = (const int*)d_in[2];
    const float* emb_W = (const float*)d_in[3];
    const float* emb_b = (const float*)d_in[4];
    const float* eW1   = (const float*)d_in[5];
    const float* eb1   = (const float*)d_in[6];
    const float* eW2   = (const float*)d_in[7];
    const float* eb2   = (const float*)d_in[8];
    const float* nW1   = (const float*)d_in[9];
    const float* nb1   = (const float*)d_in[10];
    const float* nW2   = (const float*)d_in[11];
    const float* nb2   = (const float*)d_in[12];
    const float* cW1   = (const float*)d_in[13];
    const float* cb1   = (const float*)d_in[14];
    const float* cW2   = (const float*)d_in[15];
    const float* cb2   = (const float*)d_in[16];
    float* out = (float*)d_out;

    cudaFuncSetAttribute(edge_kernel, cudaFuncAttributeMaxDynamicSharedMemorySize, EDGE_SMEM_BYTES);
    cudaFuncSetAttribute(node_kernel, cudaFuncAttributeMaxDynamicSharedMemorySize, NODE_SMEM_BYTES);

    xcopy_kernel<<<(NN * 3 + 255) / 256, 256>>>(x_in);
    embed_kernel<<<(NN * HH + 255) / 256, 256>>>(h_in, emb_W, emb_b);
    prep_kernel<<<(7 * 8192 + 255) / 256, 256>>>(eW1, eW2, cW1, nW1, nW2);

    for (int l = 0; l < 2; l++) {
        zero_kernel<<<(NN * HH + 255) / 256, 256>>>();
        edge_kernel<<<EE / TE, NT, EDGE_SMEM_BYTES>>>(ei, eb1, eb2, cb1, cW2, cb2, eW1);
        bool fin = (l == 1);
        node_kernel<<<(NN + TN - 1) / TN, NT, NODE_SMEM_BYTES>>>(
            nb1, nb2,
            fin ? out : (float*)nullptr,
            fin ? out + (size_t)NN * HH : (float*)nullptr);
    }
}

// round 8
// speedup vs baseline: 9.7493x; 1.1777x over previous
#include <cuda_runtime.h>
#include <cuda_fp16.h>
#include <cstdint>

#define NN 20000
#define EE 640000
#define HH 128
#define TE 128          // edges per block (edge kernel)
#define NT 256
#define TN 64           // nodes per block (node kernel)

// Scratch state (device globals: no allocation allowed)
__device__ float g_h[NN * HH];
__device__ float g_x[NN * 3];
__device__ float g_m[NN * HH];
__device__ float g_xacc[NN * 3];
// fp16-packed transposed weights, chunk-major [4][128n][16kpair] uint32 each:
// 0=eW1[0:128] 1=eW1[128:256] 2=eW2 3=cW1 4=nW1[0:128] 5=nW1[128:256] 6=nW2
__device__ uint32_t g_wp[7 * 8192];

// ===========================================================================
// helpers
// ===========================================================================
__device__ __forceinline__ uint32_t pack_h2(float a, float b) {
    __half2 h = __floats2half2_rn(a, b);
    return *(uint32_t*)&h;
}

__device__ __forceinline__ void mma16h(float* c,
                                       uint32_t a0, uint32_t a1, uint32_t a2, uint32_t a3,
                                       uint32_t b0, uint32_t b1) {
    asm volatile(
        "mma.sync.aligned.m16n8k16.row.col.f32.f16.f16.f32 "
        "{%0,%1,%2,%3}, {%4,%5,%6,%7}, {%8,%9}, {%0,%1,%2,%3};"
        : "+f"(c[0]), "+f"(c[1]), "+f"(c[2]), "+f"(c[3])
        : "r"(a0), "r"(a1), "r"(a2), "r"(a3), "r"(b0), "r"(b1));
}

// ===========================================================================
// smem layouts (uint32 indices)
// ===========================================================================
#define PAH 68            // A pitch in uint32 kpairs: (4g+t)%32 distinct
#define PWH 20            // W pitch in uint32 kpairs: (20g+t)%32 distinct
// edge kernel (TE=128)
#define S_AROW 0                          // 128*68 = 8704
#define S_ACOL (S_AROW + TE * PAH)        // 8704
#define S_WBUF (S_ACOL + TE * PAH)        // 2*128*20 = 5120
#define S_EB1  (S_WBUF + 2 * 128 * PWH)   // 128 (floats)
#define S_EB2  (S_EB1 + 128)
#define S_CB1  (S_EB2 + 128)
#define S_CW2  (S_CB1 + 128)
#define S_W1L  (S_CW2 + 128)
#define S_SROW (S_W1L + 128)              // int[128]
#define S_SCOL (S_SROW + TE)
#define S_SREL (S_SCOL + TE)              // 128*3 floats
#define S_SRD  (S_SREL + TE * 3)          // 128
#define S_PART (S_SRD + TE)               // 128*2
#define S_TOT  (S_PART + TE * 2)
#define EDGE_SMEM_BYTES (S_TOT * 4)
// node kernel (TN=64)
#define N_AH   0
#define N_AM   (N_AH + TN * PAH)
#define N_WBUF (N_AM + TN * PAH)
#define N_B1   (N_WBUF + 2 * 128 * PWH)
#define N_B2   (N_B1 + 128)
#define N_TOT  (N_B2 + 128)
#define NODE_SMEM_BYTES (N_TOT * 4)

// ---------------------------------------------------------------------------
// fp16 GEMM pass (edge): acc[2][8][4] += As[128,128] @ W[128,128] (32x64 warp)
// As: smem packed half2 [row][kpair] pitch PAH. Wg: global chunk-major packed.
// Double-buffered K=32 chunks. B frags reused across both m16 tiles.
// ---------------------------------------------------------------------------
__device__ __forceinline__ void gemm_pass_e(const uint32_t* __restrict__ As,
                                            const uint32_t* __restrict__ Wg,
                                            uint32_t* __restrict__ Wbuf,
                                            float acc[2][8][4],
                                            int tid, int lane, int m_base, int n_base)
{
    const int g = lane >> 2, t = lane & 3;

    uint4 pre0 = ((const uint4*)Wg)[tid];
    uint4 pre1 = ((const uint4*)Wg)[tid + 256];
    *(uint4*)&Wbuf[(tid >> 2) * PWH + (tid & 3) * 4] = pre0;
    *(uint4*)&Wbuf[((tid + 256) >> 2) * PWH + (tid & 3) * 4] = pre1;
    __syncthreads();

    for (int ch = 0; ch < 4; ch++) {
        const int cur = ch & 1;
        if (ch < 3) {
            pre0 = ((const uint4*)(Wg + (ch + 1) * 2048))[tid];
            pre1 = ((const uint4*)(Wg + (ch + 1) * 2048))[tid + 256];
        }
        const uint32_t* Wc = Wbuf + cur * (128 * PWH);
#pragma unroll
        for (int ks = 0; ks < 2; ks++) {
            const int kp = ch * 16 + ks * 8;
            const uint32_t* A0 = As + (m_base + g) * PAH + kp + t;
            uint32_t a00 = A0[0], a01 = A0[8 * PAH], a02 = A0[4], a03 = A0[8 * PAH + 4];
            const uint32_t* A1 = A0 + 16 * PAH;
            uint32_t a10 = A1[0], a11 = A1[8 * PAH], a12 = A1[4], a13 = A1[8 * PAH + 4];
            const int kb = ks * 8;
#pragma unroll
            for (int nt = 0; nt < 8; nt++) {
                const uint32_t* Bb = Wc + (n_base + nt * 8 + g) * PWH + kb + t;
                uint32_t b0 = Bb[0];
                uint32_t b1 = Bb[4];
                mma16h(acc[0][nt], a00, a01, a02, a03, b0, b1);
                mma16h(acc[1][nt], a10, a11, a12, a13, b0, b1);
            }
        }
        if (ch < 3) {
            uint32_t* dst = Wbuf + (cur ^ 1) * (128 * PWH);
            *(uint4*)&dst[(tid >> 2) * PWH + (tid & 3) * 4] = pre0;
            *(uint4*)&dst[((tid + 256) >> 2) * PWH + (tid & 3) * 4] = pre1;
        }
        __syncthreads();
    }
}

__device__ __forceinline__ void zacc_e(float acc[2][8][4]) {
#pragma unroll
    for (int m = 0; m < 2; m++)
#pragma unroll
        for (int n = 0; n < 8; n++)
#pragma unroll
            for (int j = 0; j < 4; j++) acc[m][n][j] = 0.0f;
}

// node-side pass (unchanged warp tile 32x32)
__device__ __forceinline__ void gemm_pass_h(const uint32_t* __restrict__ As,
                                            const uint32_t* __restrict__ Wg,
                                            uint32_t* __restrict__ Wbuf,
                                            float acc[2][4][4],
                                            int tid, int lane, int m_base, int n_base)
{
    const int g = lane >> 2, t = lane & 3;

    uint4 pre0 = ((const uint4*)Wg)[tid];
    uint4 pre1 = ((const uint4*)Wg)[tid + 256];
    *(uint4*)&Wbuf[(tid >> 2) * PWH + (tid & 3) * 4] = pre0;
    *(uint4*)&Wbuf[((tid + 256) >> 2) * PWH + (tid & 3) * 4] = pre1;
    __syncthreads();

    for (int ch = 0; ch < 4; ch++) {
        const int cur = ch & 1;
        if (ch < 3) {
            pre0 = ((const uint4*)(Wg + (ch + 1) * 2048))[tid];
            pre1 = ((const uint4*)(Wg + (ch + 1) * 2048))[tid + 256];
        }
        const uint32_t* Wc = Wbuf + cur * (128 * PWH);
#pragma unroll
        for (int ks = 0; ks < 2; ks++) {
            const int kp = ch * 16 + ks * 8;
            const uint32_t* A0 = As + (m_base + g) * PAH + kp + t;
            uint32_t a00 = A0[0], a01 = A0[8 * PAH], a02 = A0[4], a03 = A0[8 * PAH + 4];
            const uint32_t* A1 = A0 + 16 * PAH;
            uint32_t a10 = A1[0], a11 = A1[8 * PAH], a12 = A1[4], a13 = A1[8 * PAH + 4];
            const int kb = ks * 8;
#pragma unroll
            for (int nt = 0; nt < 4; nt++) {
                const uint32_t* Bb = Wc + (n_base + nt * 8 + g) * PWH + kb + t;
                uint32_t b0 = Bb[0];
                uint32_t b1 = Bb[4];
                mma16h(acc[0][nt], a00, a01, a02, a03, b0, b1);
                mma16h(acc[1][nt], a10, a11, a12, a13, b0, b1);
            }
        }
        if (ch < 3) {
            uint32_t* dst = Wbuf + (cur ^ 1) * (128 * PWH);
            *(uint4*)&dst[(tid >> 2) * PWH + (tid & 3) * 4] = pre0;
            *(uint4*)&dst[((tid + 256) >> 2) * PWH + (tid & 3) * 4] = pre1;
        }
        __syncthreads();
    }
}

__device__ __forceinline__ void zacc(float acc[2][4][4]) {
#pragma unroll
    for (int m = 0; m < 2; m++)
#pragma unroll
        for (int n = 0; n < 4; n++)
#pragma unroll
            for (int j = 0; j < 4; j++) acc[m][n][j] = 0.0f;
}

// prep: fp16-pack all 7 weight tiles, transposed [n][k], chunk-major
__global__ void prep_kernel(const float* __restrict__ eW1,
                            const float* __restrict__ eW2,
                            const float* __restrict__ cW1,
                            const float* __restrict__ nW1,
                            const float* __restrict__ nW2)
{
    int idx = blockIdx.x * blockDim.x + threadIdx.x;
    if (idx >= 7 * 8192) return;
    int mat = idx >> 13;
    int rem = idx & 8191;
    int chunk = rem >> 11;
    int n = (rem >> 4) & 127;
    int kp = rem & 15;
    int k = chunk * 32 + kp * 2;
    const float* W;
    int off = 0;
    switch (mat) {
        case 0: W = eW1; break;
        case 1: W = eW1; off = 128 * 128; break;
        case 2: W = eW2; break;
        case 3: W = cW1; break;
        case 4: W = nW1; break;
        case 5: W = nW1; off = 128 * 128; break;
        default: W = nW2; break;
    }
    g_wp[idx] = pack_h2(W[off + k * 128 + n], W[off + (k + 1) * 128 + n]);
}

// ---------------------------------------------------------------------------
// Fused edge pass. 128-edge tile, 8 warps (4 M x 2 N groups), 2 CTA/SM.
// ---------------------------------------------------------------------------
__global__ void __launch_bounds__(NT, 2) edge_kernel(
    const int* __restrict__ ei,
    const float* __restrict__ eb1, const float* __restrict__ eb2,
    const float* __restrict__ cb1, const float* __restrict__ cW2,
    const float* __restrict__ cb2, const float* __restrict__ eW1)
{
    extern __shared__ uint32_t smu[];
    float* smf = (float*)smu;
    uint32_t* Arow = smu + S_AROW;
    uint32_t* Acol = smu + S_ACOL;      // becomes C1
    uint32_t* Wbuf = smu + S_WBUF;
    int*   srow = (int*)(smu + S_SROW);
    int*   scol = (int*)(smu + S_SCOL);
    float* srel = smf + S_SREL;
    float* srd  = smf + S_SRD;
    float* spart= smf + S_PART;

    const int tid  = threadIdx.x;
    const int lane = tid & 31;
    const int wid  = tid >> 5;
    const int m_base = (wid & 3) * 32;
    const int n_base = (wid >> 2) * 64;
    const int wn = wid >> 2;
    const int g = lane >> 2, t = lane & 3;
    const int e0 = blockIdx.x * TE;

    if (tid < TE) {
        int e = e0 + tid;
        int r = ei[e];
        int c = ei[EE + e];
        if ((unsigned)r >= NN) r = 0;
        if ((unsigned)c >= NN) c = 0;
        srow[tid] = r;
        scol[tid] = c;
        float dx = g_x[r * 3 + 0] - g_x[c * 3 + 0];
        float dy = g_x[r * 3 + 1] - g_x[c * 3 + 1];
        float dz = g_x[r * 3 + 2] - g_x[c * 3 + 2];
        srel[tid * 3 + 0] = dx; srel[tid * 3 + 1] = dy; srel[tid * 3 + 2] = dz;
        srd[tid] = dx * dx + dy * dy + dz * dz;
    }
    if (tid < 128) {
        smf[S_EB1 + tid] = eb1[tid];
        smf[S_EB2 + tid] = eb2[tid];
        smf[S_CB1 + tid] = cb1[tid];
        smf[S_CW2 + tid] = cW2[tid];
        smf[S_W1L + tid] = eW1[256 * 128 + tid];
    }
    __syncthreads();

    // gather h[row], h[col] -> fp16-packed tiles (L2-resident)
    for (int j = tid; j < TE * 32; j += NT) {
        int e = j >> 5, c4 = j & 31;
        float4 hr = ((const float4*)(g_h + (size_t)srow[e] * HH))[c4];
        float4 hc = ((const float4*)(g_h + (size_t)scol[e] * HH))[c4];
        *(uint2*)&Arow[e * PAH + c4 * 2] =
            make_uint2(pack_h2(hr.x, hr.y), pack_h2(hr.z, hr.w));
        *(uint2*)&Acol[e * PAH + c4 * 2] =
            make_uint2(pack_h2(hc.x, hc.y), pack_h2(hc.z, hc.w));
    }
    // (gemm_pass_e's first __syncthreads covers the gather)

    float acc[2][8][4];

    // ---- GEMM1: h_row @ W1a + h_col @ W1b ----
    zacc_e(acc);
    gemm_pass_e(Arow, g_wp,        Wbuf, acc, tid, lane, m_base, n_base);
    gemm_pass_e(Acol, g_wp + 8192, Wbuf, acc, tid, lane, m_base, n_base);

    // epilogue 1: + rd*w1_last + bias, relu -> fp16 C1 (Acol reuse)
#pragma unroll
    for (int m = 0; m < 2; m++) {
        const int r0 = m_base + m * 16 + g, r1 = r0 + 8;
        float d0 = srd[r0], d1 = srd[r1];
#pragma unroll
        for (int nt = 0; nt < 8; nt++) {
            int c = n_base + nt * 8 + t * 2;
            float bA = smf[S_EB1 + c], bB = smf[S_EB1 + c + 1];
            float wA = smf[S_W1L + c], wB = smf[S_W1L + c + 1];
            Acol[r0 * PAH + (c >> 1)] = pack_h2(fmaxf(acc[m][nt][0] + bA + d0 * wA, 0.0f),
                                                fmaxf(acc[m][nt][1] + bB + d0 * wB, 0.0f));
            Acol[r1 * PAH + (c >> 1)] = pack_h2(fmaxf(acc[m][nt][2] + bA + d1 * wA, 0.0f),
                                                fmaxf(acc[m][nt][3] + bB + d1 * wB, 0.0f));
        }
    }

    // ---- GEMM2: E2 = C1 @ eW2 ---- (first internal sync orders C1 writes)
    zacc_e(acc);
    gemm_pass_e(Acol, g_wp + 2 * 8192, Wbuf, acc, tid, lane, m_base, n_base);

    // epilogue 2: +bias -> atomic g_m[row]; fp16 stash -> Arow
#pragma unroll
    for (int m = 0; m < 2; m++) {
        const int r0 = m_base + m * 16 + g, r1 = r0 + 8;
        float* m0 = g_m + (size_t)srow[r0] * HH;
        float* m1 = g_m + (size_t)srow[r1] * HH;
#pragma unroll
        for (int nt = 0; nt < 8; nt++) {
            int c = n_base + nt * 8 + t * 2;
            float bA = smf[S_EB2 + c], bB = smf[S_EB2 + c + 1];
            float v00 = acc[m][nt][0] + bA, v01 = acc[m][nt][1] + bB;
            float v10 = acc[m][nt][2] + bA, v11 = acc[m][nt][3] + bB;
            atomicAdd(&m0[c], v00);  atomicAdd(&m0[c + 1], v01);
            atomicAdd(&m1[c], v10);  atomicAdd(&m1[c + 1], v11);
            Arow[r0 * PAH + (c >> 1)] = pack_h2(v00, v01);
            Arow[r1 * PAH + (c >> 1)] = pack_h2(v10, v11);
        }
    }

    // ---- GEMM3: C3 = relu(E2 @ cW1 + cb1); alpha = C3 . cW2 + cb2 ----
    zacc_e(acc);
    gemm_pass_e(Arow, g_wp + 3 * 8192, Wbuf, acc, tid, lane, m_base, n_base);
#pragma unroll
    for (int m = 0; m < 2; m++) {
        const int r0 = m_base + m * 16 + g;
        float p0 = 0.0f, p1 = 0.0f;
#pragma unroll
        for (int nt = 0; nt < 8; nt++) {
            int c = n_base + nt * 8 + t * 2;
            float bA = smf[S_CB1 + c], bB = smf[S_CB1 + c + 1];
            float wA = smf[S_CW2 + c], wB = smf[S_CW2 + c + 1];
            p0 = fmaf(fmaxf(acc[m][nt][0] + bA, 0.0f), wA, p0);
            p0 = fmaf(fmaxf(acc[m][nt][1] + bB, 0.0f), wB, p0);
            p1 = fmaf(fmaxf(acc[m][nt][2] + bA, 0.0f), wA, p1);
            p1 = fmaf(fmaxf(acc[m][nt][3] + bB, 0.0f), wB, p1);
        }
        p0 += __shfl_xor_sync(0xffffffffu, p0, 1);
        p0 += __shfl_xor_sync(0xffffffffu, p0, 2);
        p1 += __shfl_xor_sync(0xffffffffu, p1, 1);
        p1 += __shfl_xor_sync(0xffffffffu, p1, 2);
        if (t == 0) {
            spart[r0 * 2 + wn]       = p0;
            spart[(r0 + 8) * 2 + wn] = p1;
        }
    }
    __syncthreads();

    if (tid < TE) {
        float alpha = spart[tid * 2] + spart[tid * 2 + 1] + cb2[0];
        int node = srow[tid];
        atomicAdd(&g_xacc[node * 3 + 0], alpha * srel[tid * 3 + 0]);
        atomicAdd(&g_xacc[node * 3 + 1], alpha * srel[tid * 3 + 1]);
        atomicAdd(&g_xacc[node * 3 + 2], alpha * srel[tid * 3 + 2]);
    }
}

// ---------------------------------------------------------------------------
// Node update (fp16 tensor): h += relu([h,m] @ nW1 + nb1) @ nW2 + nb2; x += xacc
// ---------------------------------------------------------------------------
__global__ void __launch_bounds__(NT, 3) node_kernel(
    const float* __restrict__ nb1, const float* __restrict__ nb2,
    float* __restrict__ out_h, float* __restrict__ out_x)
{
    extern __shared__ uint32_t smu[];
    float* smf = (float*)smu;
    uint32_t* AH   = smu + N_AH;        // h fp16; reused as C1
    uint32_t* AM   = smu + N_AM;        // m fp16
    uint32_t* Wbuf = smu + N_WBUF;

    const int tid  = threadIdx.x;
    const int lane = tid & 31;
    const int wid  = tid >> 5;
    const int m_base = (wid & 1) * 32;
    const int n_base = (wid >> 1) * 32;
    const int g = lane >> 2, t = lane & 3;
    const int n0 = blockIdx.x * TN;

    if (tid < 128) {
        smf[N_B1 + tid] = nb1[tid];
        smf[N_B2 + tid] = nb2[tid];
    }

    for (int j = tid; j < TN * 32; j += NT) {
        int e = j >> 5, c4 = j & 31;
        int n = n0 + e; if (n >= NN) n = NN - 1;
        float4 hv = ((const float4*)(g_h + (size_t)n * HH))[c4];
        float4 mv = ((const float4*)(g_m + (size_t)n * HH))[c4];
        *(uint2*)&AH[e * PAH + c4 * 2] =
            make_uint2(pack_h2(hv.x, hv.y), pack_h2(hv.z, hv.w));
        *(uint2*)&AM[e * PAH + c4 * 2] =
            make_uint2(pack_h2(mv.x, mv.y), pack_h2(mv.z, mv.w));
    }

    float acc[2][4][4];

    // GEMM1: [h|m] @ nW1 (K=256 as two accumulating K=128 passes)
    zacc(acc);
    gemm_pass_h(AH, g_wp + 4 * 8192, Wbuf, acc, tid, lane, m_base, n_base);
    gemm_pass_h(AM, g_wp + 5 * 8192, Wbuf, acc, tid, lane, m_base, n_base);

    // epilogue 1: relu(+nb1) -> fp16 into AH (reused as C1)
#pragma unroll
    for (int m = 0; m < 2; m++) {
        const int r0 = m_base + m * 16 + g, r1 = r0 + 8;
#pragma unroll
        for (int nt = 0; nt < 4; nt++) {
            int c = n_base + nt * 8 + t * 2;
            float bA = smf[N_B1 + c], bB = smf[N_B1 + c + 1];
            AH[r0 * PAH + (c >> 1)] = pack_h2(fmaxf(acc[m][nt][0] + bA, 0.0f),
                                              fmaxf(acc[m][nt][1] + bB, 0.0f));
            AH[r1 * PAH + (c >> 1)] = pack_h2(fmaxf(acc[m][nt][2] + bA, 0.0f),
                                              fmaxf(acc[m][nt][3] + bB, 0.0f));
        }
    }

    // GEMM2: C1 @ nW2
    zacc(acc);
    gemm_pass_h(AH, g_wp + 6 * 8192, Wbuf, acc, tid, lane, m_base, n_base);

    // epilogue 2: h_new = h_old + acc + nb2 -> g_h (+ out)
#pragma unroll
    for (int m = 0; m < 2; m++) {
#pragma unroll
        for (int half = 0; half < 2; half++) {
            const int r = m_base + m * 16 + g + half * 8;
            const int n = n0 + r;
            if (n < NN) {
#pragma unroll
                for (int nt = 0; nt < 4; nt++) {
                    int c = n_base + nt * 8 + t * 2;
                    float a0 = acc[m][nt][half * 2 + 0];
                    float a1 = acc[m][nt][half * 2 + 1];
                    float h0 = g_h[(size_t)n * HH + c]     + a0 + smf[N_B2 + c];
                    float h1 = g_h[(size_t)n * HH + c + 1] + a1 + smf[N_B2 + c + 1];
                    g_h[(size_t)n * HH + c]     = h0;
                    g_h[(size_t)n * HH + c + 1] = h1;
                    if (out_h) {
                        out_h[(size_t)n * HH + c]     = h0;
                        out_h[(size_t)n * HH + c + 1] = h1;
                    }
                }
            }
        }
    }

    for (int tt = tid; tt < TN * 3; tt += NT) {
        int n = n0 + tt / 3;
        if (n < NN) {
            int d = tt % 3;
            float xv = g_x[n * 3 + d] + g_xacc[n * 3 + d];
            g_x[n * 3 + d] = xv;
            if (out_x) out_x[n * 3 + d] = xv;
        }
    }
}

// ===========================================================================
// small setup kernels
// ===========================================================================
__global__ void embed_kernel(const float* __restrict__ hin,
                             const float* __restrict__ W,
                             const float* __restrict__ b)
{
    int j = blockIdx.x * blockDim.x + threadIdx.x;
    if (j >= NN * HH) return;
    int n = j >> 7, c = j & 127;
    float acc = b[c];
#pragma unroll
    for (int k = 0; k < 16; k++)
        acc = fmaf(hin[n * 16 + k], W[k * 128 + c], acc);
    g_h[j] = acc;
}

__global__ void xcopy_kernel(const float* __restrict__ xin)
{
    int i = blockIdx.x * blockDim.x + threadIdx.x;
    if (i < NN * 3) g_x[i] = xin[i];
}

__global__ void zero_kernel()
{
    int i = blockIdx.x * blockDim.x + threadIdx.x;
    if (i < NN * HH) g_m[i] = 0.0f;
    if (i < NN * 3) g_xacc[i] = 0.0f;
}

extern "C" void kernel_launch(void* const* d_in, const int* in_sizes, int n_in,
                              void* d_out, int out_size)
{
    const float* h_in  = (const float*)d_in[0];
    const float* x_in  = (const float*)d_in[1];
    const int*   ei    = (const int*)d_in[2];
    const float* emb_W = (const float*)d_in[3];
    const float* emb_b = (const float*)d_in[4];
    const float* eW1   = (const float*)d_in[5];
    const float* eb1   = (const float*)d_in[6];
    const float* eW2   = (const float*)d_in[7];
    const float* eb2   = (const float*)d_in[8];
    const float* nW1   = (const float*)d_in[9];
    const float* nb1   = (const float*)d_in[10];
    const float* nW2   = (const float*)d_in[11];
    const float* nb2   = (const float*)d_in[12];
    const float* cW1   = (const float*)d_in[13];
    const float* cb1   = (const float*)d_in[14];
    const float* cW2   = (const float*)d_in[15];
    const float* cb2   = (const float*)d_in[16];
    float* out = (float*)d_out;

    cudaFuncSetAttribute(edge_kernel, cudaFuncAttributeMaxDynamicSharedMemorySize, EDGE_SMEM_BYTES);
    cudaFuncSetAttribute(node_kernel, cudaFuncAttributeMaxDynamicSharedMemorySize, NODE_SMEM_BYTES);

    xcopy_kernel<<<(NN * 3 + 255) / 256, 256>>>(x_in);
    embed_kernel<<<(NN * HH + 255) / 256, 256>>>(h_in, emb_W, emb_b);
    prep_kernel<<<(7 * 8192 + 255) / 256, 256>>>(eW1, eW2, cW1, nW1, nW2);

    for (int l = 0; l < 2; l++) {
        zero_kernel<<<(NN * HH + 255) / 256, 256>>>();
        edge_kernel<<<EE / TE, NT, EDGE_SMEM_BYTES>>>(ei, eb1, eb2, cb1, cW2, cb2, eW1);
        bool fin = (l == 1);
        node_kernel<<<(NN + TN - 1) / TN, NT, NODE_SMEM_BYTES>>>(
            nb1, nb2,
            fin ? out : (float*)nullptr,
            fin ? out + (size_t)NN * HH : (float*)nullptr);
    }
}

// round 9
// speedup vs baseline: 9.7967x; 1.0049x over previous
#include <cuda_runtime.h>
#include <cuda_fp16.h>
#include <cstdint>

#define NN 20000
#define EE 640000
#define HH 128
#define TE 128          // edges per block (edge kernel)
#define NT 256
#define TN 64           // nodes per block (node kernel)

// Scratch state (device globals: no allocation allowed)
__device__ float g_h[NN * HH];
__device__ float g_x[NN * 3];
__device__ float g_m[NN * HH];
__device__ float g_xacc[NN * 3];
// fp16-packed transposed weights, chunk-major [4][128n][16kpair] uint32 each:
// 0=eW1[0:128] 1=eW1[128:256] 2=eW2 3=cW1 4=nW1[0:128] 5=nW1[128:256] 6=nW2
__device__ uint32_t g_wp[7 * 8192];

// ===========================================================================
// helpers
// ===========================================================================
__device__ __forceinline__ uint32_t pack_h2(float a, float b) {
    __half2 h = __floats2half2_rn(a, b);
    return *(uint32_t*)&h;
}

__device__ __forceinline__ void mma16h(float* c,
                                       uint32_t a0, uint32_t a1, uint32_t a2, uint32_t a3,
                                       uint32_t b0, uint32_t b1) {
    asm volatile(
        "mma.sync.aligned.m16n8k16.row.col.f32.f16.f16.f32 "
        "{%0,%1,%2,%3}, {%4,%5,%6,%7}, {%8,%9}, {%0,%1,%2,%3};"
        : "+f"(c[0]), "+f"(c[1]), "+f"(c[2]), "+f"(c[3])
        : "r"(a0), "r"(a1), "r"(a2), "r"(a3), "r"(b0), "r"(b1));
}

// ===========================================================================
// smem layouts (uint32 indices)
// ===========================================================================
#define PAH 68            // A pitch in uint32 kpairs: (4g+t)%32 distinct
// W buffer: full 128x128 fp16 tile = 8192 u32, XOR-swizzled (no padding):
//   u32 index of (chunk, n, kp) = chunk*2048 + n*16 + (kp ^ (((n>>1)&3)<<2))
// edge kernel (TE=128)
#define S_AROW 0                          // 128*68 = 8704
#define S_ACOL (S_AROW + TE * PAH)        // 8704
#define S_WBUF (S_ACOL + TE * PAH)        // 8192
#define S_EB1  (S_WBUF + 8192)            // 128 (floats)
#define S_EB2  (S_EB1 + 128)
#define S_CB1  (S_EB2 + 128)
#define S_CW2  (S_CB1 + 128)
#define S_W1L  (S_CW2 + 128)
#define S_SROW (S_W1L + 128)              // int[128]
#define S_SCOL (S_SROW + TE)
#define S_SREL (S_SCOL + TE)              // 128*3 floats
#define S_SRD  (S_SREL + TE * 3)          // 128
#define S_PART (S_SRD + TE)               // 128*2
#define S_TOT  (S_PART + TE * 2)
#define EDGE_SMEM_BYTES (S_TOT * 4)
// node kernel (TN=64)
#define N_AH   0
#define N_AM   (N_AH + TN * PAH)
#define N_WBUF (N_AM + TN * PAH)
#define N_B1   (N_WBUF + 8192)
#define N_B2   (N_B1 + 128)
#define N_TOT  (N_B2 + 128)
#define NODE_SMEM_BYTES (N_TOT * 4)

// stage full 128x128 W tile into swizzled smem (2048 uint4s, 8/thread)
__device__ __forceinline__ void stage_w(const uint32_t* __restrict__ Wg,
                                        uint32_t* __restrict__ Wbuf, int tid)
{
    __syncthreads();        // prior Wbuf readers done; orders A-tile epilogue writes
#pragma unroll
    for (int i = 0; i < 8; i++) {
        int j = tid + 256 * i;
        int chunk = j >> 9;
        int n = (j >> 2) & 127;
        int kq = j & 3;
        *(uint4*)&Wbuf[chunk * 2048 + n * 16 + 4 * (kq ^ ((n >> 1) & 3))] =
            ((const uint4*)Wg)[j];
    }
    __syncthreads();
}

// ---------------------------------------------------------------------------
// fp16 GEMM pass (edge): acc[2][8][4] += As[128,128] @ W[128,128] (32x64 warp)
// Whole W staged once; 128 MMAs with no internal barriers.
// ---------------------------------------------------------------------------
__device__ __forceinline__ void gemm_pass_e(const uint32_t* __restrict__ As,
                                            const uint32_t* __restrict__ Wg,
                                            uint32_t* __restrict__ Wbuf,
                                            float acc[2][8][4],
                                            int tid, int lane, int m_base, int n_base)
{
    const int g = lane >> 2, t = lane & 3;
    const int s = ((g >> 1) & 3) << 2;

    stage_w(Wg, Wbuf, tid);

#pragma unroll
    for (int ch = 0; ch < 4; ch++) {
        const uint32_t* Wc = Wbuf + ch * 2048;
#pragma unroll
        for (int ks = 0; ks < 2; ks++) {
            const int kp = ch * 16 + ks * 8;
            const uint32_t* A0 = As + (m_base + g) * PAH + kp + t;
            uint32_t a00 = A0[0], a01 = A0[8 * PAH], a02 = A0[4], a03 = A0[8 * PAH + 4];
            const uint32_t* A1 = A0 + 16 * PAH;
            uint32_t a10 = A1[0], a11 = A1[8 * PAH], a12 = A1[4], a13 = A1[8 * PAH + 4];
            const int kb = ks * 8;
#pragma unroll
            for (int nt = 0; nt < 8; nt++) {
                const uint32_t* Bb = Wc + (n_base + nt * 8 + g) * 16;
                uint32_t b0 = Bb[(kb + t) ^ s];
                uint32_t b1 = Bb[(kb + t + 4) ^ s];
                mma16h(acc[0][nt], a00, a01, a02, a03, b0, b1);
                mma16h(acc[1][nt], a10, a11, a12, a13, b0, b1);
            }
        }
    }
}

__device__ __forceinline__ void zacc_e(float acc[2][8][4]) {
#pragma unroll
    for (int m = 0; m < 2; m++)
#pragma unroll
        for (int n = 0; n < 8; n++)
#pragma unroll
            for (int j = 0; j < 4; j++) acc[m][n][j] = 0.0f;
}

// node-side pass (warp tile 32x32)
__device__ __forceinline__ void gemm_pass_h(const uint32_t* __restrict__ As,
                                            const uint32_t* __restrict__ Wg,
                                            uint32_t* __restrict__ Wbuf,
                                            float acc[2][4][4],
                                            int tid, int lane, int m_base, int n_base)
{
    const int g = lane >> 2, t = lane & 3;
    const int s = ((g >> 1) & 3) << 2;

    stage_w(Wg, Wbuf, tid);

#pragma unroll
    for (int ch = 0; ch < 4; ch++) {
        const uint32_t* Wc = Wbuf + ch * 2048;
#pragma unroll
        for (int ks = 0; ks < 2; ks++) {
            const int kp = ch * 16 + ks * 8;
            const uint32_t* A0 = As + (m_base + g) * PAH + kp + t;
            uint32_t a00 = A0[0], a01 = A0[8 * PAH], a02 = A0[4], a03 = A0[8 * PAH + 4];
            const uint32_t* A1 = A0 + 16 * PAH;
            uint32_t a10 = A1[0], a11 = A1[8 * PAH], a12 = A1[4], a13 = A1[8 * PAH + 4];
            const int kb = ks * 8;
#pragma unroll
            for (int nt = 0; nt < 4; nt++) {
                const uint32_t* Bb = Wc + (n_base + nt * 8 + g) * 16;
                uint32_t b0 = Bb[(kb + t) ^ s];
                uint32_t b1 = Bb[(kb + t + 4) ^ s];
                mma16h(acc[0][nt], a00, a01, a02, a03, b0, b1);
                mma16h(acc[1][nt], a10, a11, a12, a13, b0, b1);
            }
        }
    }
}

__device__ __forceinline__ void zacc(float acc[2][4][4]) {
#pragma unroll
    for (int m = 0; m < 2; m++)
#pragma unroll
        for (int n = 0; n < 4; n++)
#pragma unroll
            for (int j = 0; j < 4; j++) acc[m][n][j] = 0.0f;
}

// prep: fp16-pack all 7 weight tiles, transposed [n][k], chunk-major
__global__ void prep_kernel(const float* __restrict__ eW1,
                            const float* __restrict__ eW2,
                            const float* __restrict__ cW1,
                            const float* __restrict__ nW1,
                            const float* __restrict__ nW2)
{
    int idx = blockIdx.x * blockDim.x + threadIdx.x;
    if (idx >= 7 * 8192) return;
    int mat = idx >> 13;
    int rem = idx & 8191;
    int chunk = rem >> 11;
    int n = (rem >> 4) & 127;
    int kp = rem & 15;
    int k = chunk * 32 + kp * 2;
    const float* W;
    int off = 0;
    switch (mat) {
        case 0: W = eW1; break;
        case 1: W = eW1; off = 128 * 128; break;
        case 2: W = eW2; break;
        case 3: W = cW1; break;
        case 4: W = nW1; break;
        case 5: W = nW1; off = 128 * 128; break;
        default: W = nW2; break;
    }
    g_wp[idx] = pack_h2(W[off + k * 128 + n], W[off + (k + 1) * 128 + n]);
}

// ---------------------------------------------------------------------------
// Fused edge pass. 128-edge tile, 8 warps (4 M x 2 N groups), 2 CTA/SM.
// ---------------------------------------------------------------------------
__global__ void __launch_bounds__(NT, 2) edge_kernel(
    const int* __restrict__ ei,
    const float* __restrict__ eb1, const float* __restrict__ eb2,
    const float* __restrict__ cb1, const float* __restrict__ cW2,
    const float* __restrict__ cb2, const float* __restrict__ eW1)
{
    extern __shared__ uint32_t smu[];
    float* smf = (float*)smu;
    uint32_t* Arow = smu + S_AROW;
    uint32_t* Acol = smu + S_ACOL;      // becomes C1
    uint32_t* Wbuf = smu + S_WBUF;
    int*   srow = (int*)(smu + S_SROW);
    int*   scol = (int*)(smu + S_SCOL);
    float* srel = smf + S_SREL;
    float* srd  = smf + S_SRD;
    float* spart= smf + S_PART;

    const int tid  = threadIdx.x;
    const int lane = tid & 31;
    const int wid  = tid >> 5;
    const int m_base = (wid & 3) * 32;
    const int n_base = (wid >> 2) * 64;
    const int wn = wid >> 2;
    const int g = lane >> 2, t = lane & 3;
    const int e0 = blockIdx.x * TE;

    if (tid < TE) {
        int e = e0 + tid;
        int r = ei[e];
        int c = ei[EE + e];
        if ((unsigned)r >= NN) r = 0;
        if ((unsigned)c >= NN) c = 0;
        srow[tid] = r;
        scol[tid] = c;
        float dx = g_x[r * 3 + 0] - g_x[c * 3 + 0];
        float dy = g_x[r * 3 + 1] - g_x[c * 3 + 1];
        float dz = g_x[r * 3 + 2] - g_x[c * 3 + 2];
        srel[tid * 3 + 0] = dx; srel[tid * 3 + 1] = dy; srel[tid * 3 + 2] = dz;
        srd[tid] = dx * dx + dy * dy + dz * dz;
    }
    if (tid < 128) {
        smf[S_EB1 + tid] = eb1[tid];
        smf[S_EB2 + tid] = eb2[tid];
        smf[S_CB1 + tid] = cb1[tid];
        smf[S_CW2 + tid] = cW2[tid];
        smf[S_W1L + tid] = eW1[256 * 128 + tid];
    }
    __syncthreads();

    // gather h[row], h[col] -> fp16-packed tiles (L2-resident)
    for (int j = tid; j < TE * 32; j += NT) {
        int e = j >> 5, c4 = j & 31;
        float4 hr = ((const float4*)(g_h + (size_t)srow[e] * HH))[c4];
        float4 hc = ((const float4*)(g_h + (size_t)scol[e] * HH))[c4];
        *(uint2*)&Arow[e * PAH + c4 * 2] =
            make_uint2(pack_h2(hr.x, hr.y), pack_h2(hr.z, hr.w));
        *(uint2*)&Acol[e * PAH + c4 * 2] =
            make_uint2(pack_h2(hc.x, hc.y), pack_h2(hc.z, hc.w));
    }
    // (stage_w's first __syncthreads covers the gather)

    float acc[2][8][4];

    // ---- GEMM1: h_row @ W1a + h_col @ W1b ----
    zacc_e(acc);
    gemm_pass_e(Arow, g_wp,        Wbuf, acc, tid, lane, m_base, n_base);
    gemm_pass_e(Acol, g_wp + 8192, Wbuf, acc, tid, lane, m_base, n_base);

    // all warps must finish reading Acol (pass 1b) before C1 overwrites it
    __syncthreads();

    // epilogue 1: + rd*w1_last + bias, relu -> fp16 C1 (Acol reuse)
#pragma unroll
    for (int m = 0; m < 2; m++) {
        const int r0 = m_base + m * 16 + g, r1 = r0 + 8;
        float d0 = srd[r0], d1 = srd[r1];
#pragma unroll
        for (int nt = 0; nt < 8; nt++) {
            int c = n_base + nt * 8 + t * 2;
            float bA = smf[S_EB1 + c], bB = smf[S_EB1 + c + 1];
            float wA = smf[S_W1L + c], wB = smf[S_W1L + c + 1];
            Acol[r0 * PAH + (c >> 1)] = pack_h2(fmaxf(acc[m][nt][0] + bA + d0 * wA, 0.0f),
                                                fmaxf(acc[m][nt][1] + bB + d0 * wB, 0.0f));
            Acol[r1 * PAH + (c >> 1)] = pack_h2(fmaxf(acc[m][nt][2] + bA + d1 * wA, 0.0f),
                                                fmaxf(acc[m][nt][3] + bB + d1 * wB, 0.0f));
        }
    }

    // ---- GEMM2: E2 = C1 @ eW2 ---- (stage_w syncs order C1 writes)
    zacc_e(acc);
    gemm_pass_e(Acol, g_wp + 2 * 8192, Wbuf, acc, tid, lane, m_base, n_base);

    // epilogue 2: +bias -> atomic g_m[row]; fp16 stash -> Arow
    // (Arow not read during GEMM2, so no sync needed before overwriting it)
#pragma unroll
    for (int m = 0; m < 2; m++) {
        const int r0 = m_base + m * 16 + g, r1 = r0 + 8;
        float* m0 = g_m + (size_t)srow[r0] * HH;
        float* m1 = g_m + (size_t)srow[r1] * HH;
#pragma unroll
        for (int nt = 0; nt < 8; nt++) {
            int c = n_base + nt * 8 + t * 2;
            float bA = smf[S_EB2 + c], bB = smf[S_EB2 + c + 1];
            float v00 = acc[m][nt][0] + bA, v01 = acc[m][nt][1] + bB;
            float v10 = acc[m][nt][2] + bA, v11 = acc[m][nt][3] + bB;
            atomicAdd(&m0[c], v00);  atomicAdd(&m0[c + 1], v01);
            atomicAdd(&m1[c], v10);  atomicAdd(&m1[c + 1], v11);
            Arow[r0 * PAH + (c >> 1)] = pack_h2(v00, v01);
            Arow[r1 * PAH + (c >> 1)] = pack_h2(v10, v11);
        }
    }

    // ---- GEMM3: C3 = relu(E2 @ cW1 + cb1); alpha = C3 . cW2 + cb2 ----
    zacc_e(acc);
    gemm_pass_e(Arow, g_wp + 3 * 8192, Wbuf, acc, tid, lane, m_base, n_base);
#pragma unroll
    for (int m = 0; m < 2; m++) {
        const int r0 = m_base + m * 16 + g;
        float p0 = 0.0f, p1 = 0.0f;
#pragma unroll
        for (int nt = 0; nt < 8; nt++) {
            int c = n_base + nt * 8 + t * 2;
            float bA = smf[S_CB1 + c], bB = smf[S_CB1 + c + 1];
            float wA = smf[S_CW2 + c], wB = smf[S_CW2 + c + 1];
            p0 = fmaf(fmaxf(acc[m][nt][0] + bA, 0.0f), wA, p0);
            p0 = fmaf(fmaxf(acc[m][nt][1] + bB, 0.0f), wB, p0);
            p1 = fmaf(fmaxf(acc[m][nt][2] + bA, 0.0f), wA, p1);
            p1 = fmaf(fmaxf(acc[m][nt][3] + bB, 0.0f), wB, p1);
        }
        p0 += __shfl_xor_sync(0xffffffffu, p0, 1);
        p0 += __shfl_xor_sync(0xffffffffu, p0, 2);
        p1 += __shfl_xor_sync(0xffffffffu, p1, 1);
        p1 += __shfl_xor_sync(0xffffffffu, p1, 2);
        if (t == 0) {
            spart[r0 * 2 + wn]       = p0;
            spart[(r0 + 8) * 2 + wn] = p1;
        }
    }
    __syncthreads();

    if (tid < TE) {
        float alpha = spart[tid * 2] + spart[tid * 2 + 1] + cb2[0];
        int node = srow[tid];
        atomicAdd(&g_xacc[node * 3 + 0], alpha * srel[tid * 3 + 0]);
        atomicAdd(&g_xacc[node * 3 + 1], alpha * srel[tid * 3 + 1]);
        atomicAdd(&g_xacc[node * 3 + 2], alpha * srel[tid * 3 + 2]);
    }
}

// ---------------------------------------------------------------------------
// Node update (fp16 tensor): h += relu([h,m] @ nW1 + nb1) @ nW2 + nb2; x += xacc
// ---------------------------------------------------------------------------
__global__ void __launch_bounds__(NT, 3) node_kernel(
    const float* __restrict__ nb1, const float* __restrict__ nb2,
    float* __restrict__ out_h, float* __restrict__ out_x)
{
    extern __shared__ uint32_t smu[];
    float* smf = (float*)smu;
    uint32_t* AH   = smu + N_AH;        // h fp16; reused as C1
    uint32_t* AM   = smu + N_AM;        // m fp16
    uint32_t* Wbuf = smu + N_WBUF;

    const int tid  = threadIdx.x;
    const int lane = tid & 31;
    const int wid  = tid >> 5;
    const int m_base = (wid & 1) * 32;
    const int n_base = (wid >> 1) * 32;
    const int g = lane >> 2, t = lane & 3;
    const int n0 = blockIdx.x * TN;

    if (tid < 128) {
        smf[N_B1 + tid] = nb1[tid];
        smf[N_B2 + tid] = nb2[tid];
    }

    for (int j = tid; j < TN * 32; j += NT) {
        int e = j >> 5, c4 = j & 31;
        int n = n0 + e; if (n >= NN) n = NN - 1;
        float4 hv = ((const float4*)(g_h + (size_t)n * HH))[c4];
        float4 mv = ((const float4*)(g_m + (size_t)n * HH))[c4];
        *(uint2*)&AH[e * PAH + c4 * 2] =
            make_uint2(pack_h2(hv.x, hv.y), pack_h2(hv.z, hv.w));
        *(uint2*)&AM[e * PAH + c4 * 2] =
            make_uint2(pack_h2(mv.x, mv.y), pack_h2(mv.z, mv.w));
    }

    float acc[2][4][4];

    // GEMM1: [h|m] @ nW1 (K=256 as two accumulating K=128 passes)
    zacc(acc);
    gemm_pass_h(AH, g_wp + 4 * 8192, Wbuf, acc, tid, lane, m_base, n_base);
    gemm_pass_h(AM, g_wp + 5 * 8192, Wbuf, acc, tid, lane, m_base, n_base);

    // all warps must finish pass 1a reads of AH before C1 overwrites it;
    // pass-1b entry sync guarantees pass-1a completion, but warps may still
    // be in pass 1b (reads AM only) — AH writes are safe. No sync needed.

    // epilogue 1: relu(+nb1) -> fp16 into AH (reused as C1)
#pragma unroll
    for (int m = 0; m < 2; m++) {
        const int r0 = m_base + m * 16 + g, r1 = r0 + 8;
#pragma unroll
        for (int nt = 0; nt < 4; nt++) {
            int c = n_base + nt * 8 + t * 2;
            float bA = smf[N_B1 + c], bB = smf[N_B1 + c + 1];
            AH[r0 * PAH + (c >> 1)] = pack_h2(fmaxf(acc[m][nt][0] + bA, 0.0f),
                                              fmaxf(acc[m][nt][1] + bB, 0.0f));
            AH[r1 * PAH + (c >> 1)] = pack_h2(fmaxf(acc[m][nt][2] + bA, 0.0f),
                                              fmaxf(acc[m][nt][3] + bB, 0.0f));
        }
    }

    // GEMM2: C1 @ nW2  (stage_w syncs order C1 writes)
    zacc(acc);
    gemm_pass_h(AH, g_wp + 6 * 8192, Wbuf, acc, tid, lane, m_base, n_base);

    // epilogue 2: h_new = h_old + acc + nb2 -> g_h (+ out)
#pragma unroll
    for (int m = 0; m < 2; m++) {
#pragma unroll
        for (int half = 0; half < 2; half++) {
            const int r = m_base + m * 16 + g + half * 8;
            const int n = n0 + r;
            if (n < NN) {
#pragma unroll
                for (int nt = 0; nt < 4; nt++) {
                    int c = n_base + nt * 8 + t * 2;
                    float a0 = acc[m][nt][half * 2 + 0];
                    float a1 = acc[m][nt][half * 2 + 1];
                    float h0 = g_h[(size_t)n * HH + c]     + a0 + smf[N_B2 + c];
                    float h1 = g_h[(size_t)n * HH + c + 1] + a1 + smf[N_B2 + c + 1];
                    g_h[(size_t)n * HH + c]     = h0;
                    g_h[(size_t)n * HH + c + 1] = h1;
                    if (out_h) {
                        out_h[(size_t)n * HH + c]     = h0;
                        out_h[(size_t)n * HH + c + 1] = h1;
                    }
                }
            }
        }
    }

    for (int tt = tid; tt < TN * 3; tt += NT) {
        int n = n0 + tt / 3;
        if (n < NN) {
            int d = tt % 3;
            float xv = g_x[n * 3 + d] + g_xacc[n * 3 + d];
            g_x[n * 3 + d] = xv;
            if (out_x) out_x[n * 3 + d] = xv;
        }
    }
}

// ===========================================================================
// small setup kernels
// ===========================================================================
__global__ void embed_kernel(const float* __restrict__ hin,
                             const float* __restrict__ W,
                             const float* __restrict__ b)
{
    int j = blockIdx.x * blockDim.x + threadIdx.x;
    if (j >= NN * HH) return;
    int n = j >> 7, c = j & 127;
    float acc = b[c];
#pragma unroll
    for (int k = 0; k < 16; k++)
        acc = fmaf(hin[n * 16 + k], W[k * 128 + c], acc);
    g_h[j] = acc;
}

__global__ void xcopy_kernel(const float* __restrict__ xin)
{
    int i = blockIdx.x * blockDim.x + threadIdx.x;
    if (i < NN * 3) g_x[i] = xin[i];
}

__global__ void zero_kernel()
{
    int i = blockIdx.x * blockDim.x + threadIdx.x;
    if (i < NN * HH) g_m[i] = 0.0f;
    if (i < NN * 3) g_xacc[i] = 0.0f;
}

extern "C" void kernel_launch(void* const* d_in, const int* in_sizes, int n_in,
                              void* d_out, int out_size)
{
    const float* h_in  = (const float*)d_in[0];
    const float* x_in  = (const float*)d_in[1];
    const int*   ei    = (const int*)d_in[2];
    const float* emb_W = (const float*)d_in[3];
    const float* emb_b = (const float*)d_in[4];
    const float* eW1   = (const float*)d_in[5];
    const float* eb1   = (const float*)d_in[6];
    const float* eW2   = (const float*)d_in[7];
    const float* eb2   = (const float*)d_in[8];
    const float* nW1   = (const float*)d_in[9];
    const float* nb1   = (const float*)d_in[10];
    const float* nW2   = (const float*)d_in[11];
    const float* nb2   = (const float*)d_in[12];
    const float* cW1   = (const float*)d_in[13];
    const float* cb1   = (const float*)d_in[14];
    const float* cW2   = (const float*)d_in[15];
    const float* cb2   = (const float*)d_in[16];
    float* out = (float*)d_out;

    cudaFuncSetAttribute(edge_kernel, cudaFuncAttributeMaxDynamicSharedMemorySize, EDGE_SMEM_BYTES);
    cudaFuncSetAttribute(node_kernel, cudaFuncAttributeMaxDynamicSharedMemorySize, NODE_SMEM_BYTES);

    xcopy_kernel<<<(NN * 3 + 255) / 256, 256>>>(x_in);
    embed_kernel<<<(NN * HH + 255) / 256, 256>>>(h_in, emb_W, emb_b);
    prep_kernel<<<(7 * 8192 + 255) / 256, 256>>>(eW1, eW2, cW1, nW1, nW2);

    for (int l = 0; l < 2; l++) {
        zero_kernel<<<(NN * HH + 255) / 256, 256>>>();
        edge_kernel<<<EE / TE, NT, EDGE_SMEM_BYTES>>>(ei, eb1, eb2, cb1, cW2, cb2, eW1);
        bool fin = (l == 1);
        node_kernel<<<(NN + TN - 1) / TN, NT, NODE_SMEM_BYTES>>>(
            nb1, nb2,
            fin ? out : (float*)nullptr,
            fin ? out + (size_t)NN * HH : (float*)nullptr);
    }
}

// round 10
// speedup vs baseline: 10.3881x; 1.0604x over previous
#include <cuda_runtime.h>
#include <cuda_fp16.h>
#include <cstdint>

#define NN 20000
#define EE 640000
#define HH 128
#define TE 128          // edges per block (edge kernel)
#define NT 256
#define TN 64           // nodes per block (node kernel)

// Scratch state (device globals: no allocation allowed)
__device__ float g_h[NN * HH];
__device__ float g_x[NN * 3];
__device__ float g_m[NN * HH];
__device__ float g_xacc[NN * 3];
// fp16-packed transposed weights, chunk-major [4][128n][16kpair] uint32 each:
// 0=eW1[0:128] 1=eW1[128:256] 2=eW2 3=cW1 4=nW1[0:128] 5=nW1[128:256] 6=nW2
__device__ uint32_t g_wp[7 * 8192];

// ===========================================================================
// helpers
// ===========================================================================
__device__ __forceinline__ uint32_t pack_h2(float a, float b) {
    __half2 h = __floats2half2_rn(a, b);
    return *(uint32_t*)&h;
}

__device__ __forceinline__ void mma16h(float* c,
                                       uint32_t a0, uint32_t a1, uint32_t a2, uint32_t a3,
                                       uint32_t b0, uint32_t b1) {
    asm volatile(
        "mma.sync.aligned.m16n8k16.row.col.f32.f16.f16.f32 "
        "{%0,%1,%2,%3}, {%4,%5,%6,%7}, {%8,%9}, {%0,%1,%2,%3};"
        : "+f"(c[0]), "+f"(c[1]), "+f"(c[2]), "+f"(c[3])
        : "r"(a0), "r"(a1), "r"(a2), "r"(a3), "r"(b0), "r"(b1));
}

__device__ __forceinline__ void red_v4(float* p, float a, float b, float c, float d) {
    asm volatile("red.global.add.v4.f32 [%0], {%1,%2,%3,%4};"
                 :: "l"(p), "f"(a), "f"(b), "f"(c), "f"(d) : "memory");
}

// ===========================================================================
// smem layouts (uint32 indices)
// ===========================================================================
#define PAH 68            // A pitch in uint32 kpairs: (4g+t)%32 distinct
// W buffer: full 128x128 fp16 tile = 8192 u32, XOR-swizzled (no padding):
//   u32 index of (chunk, n, kp) = chunk*2048 + n*16 + (kp ^ (((n>>1)&3)<<2))
// edge kernel (TE=128)
#define S_AROW 0                          // 128*68 = 8704
#define S_ACOL (S_AROW + TE * PAH)        // 8704
#define S_WBUF (S_ACOL + TE * PAH)        // 8192
#define S_EB1  (S_WBUF + 8192)            // 128 (floats)
#define S_EB2  (S_EB1 + 128)
#define S_CB1  (S_EB2 + 128)
#define S_CW2  (S_CB1 + 128)
#define S_W1L  (S_CW2 + 128)
#define S_SROW (S_W1L + 128)              // int[128]
#define S_SCOL (S_SROW + TE)
#define S_SREL (S_SCOL + TE)              // 128*3 floats
#define S_SRD  (S_SREL + TE * 3)          // 128
#define S_PART (S_SRD + TE)               // 128*2
#define S_TOT  (S_PART + TE * 2)
#define EDGE_SMEM_BYTES (S_TOT * 4)
// node kernel (TN=64)
#define N_AH   0
#define N_AM   (N_AH + TN * PAH)
#define N_WBUF (N_AM + TN * PAH)
#define N_B1   (N_WBUF + 8192)
#define N_B2   (N_B1 + 128)
#define N_TOT  (N_B2 + 128)
#define NODE_SMEM_BYTES (N_TOT * 4)

// stage full 128x128 W tile into swizzled smem (2048 uint4s, 8/thread)
__device__ __forceinline__ void stage_w(const uint32_t* __restrict__ Wg,
                                        uint32_t* __restrict__ Wbuf, int tid)
{
    __syncthreads();        // prior Wbuf readers done; orders A-tile epilogue writes
#pragma unroll
    for (int i = 0; i < 8; i++) {
        int j = tid + 256 * i;
        int chunk = j >> 9;
        int n = (j >> 2) & 127;
        int kq = j & 3;
        *(uint4*)&Wbuf[chunk * 2048 + n * 16 + 4 * (kq ^ ((n >> 1) & 3))] =
            ((const uint4*)Wg)[j];
    }
    __syncthreads();
}

// ---------------------------------------------------------------------------
// fp16 GEMM pass (edge): acc[2][8][4] += As[128,128] @ W[128,128] (32x64 warp)
// Whole W staged once; 128 MMAs with no internal barriers.
// ---------------------------------------------------------------------------
__device__ __forceinline__ void gemm_pass_e(const uint32_t* __restrict__ As,
                                            const uint32_t* __restrict__ Wg,
                                            uint32_t* __restrict__ Wbuf,
                                            float acc[2][8][4],
                                            int tid, int lane, int m_base, int n_base)
{
    const int g = lane >> 2, t = lane & 3;
    const int s = ((g >> 1) & 3) << 2;

    stage_w(Wg, Wbuf, tid);

#pragma unroll
    for (int ch = 0; ch < 4; ch++) {
        const uint32_t* Wc = Wbuf + ch * 2048;
#pragma unroll
        for (int ks = 0; ks < 2; ks++) {
            const int kp = ch * 16 + ks * 8;
            const uint32_t* A0 = As + (m_base + g) * PAH + kp + t;
            uint32_t a00 = A0[0], a01 = A0[8 * PAH], a02 = A0[4], a03 = A0[8 * PAH + 4];
            const uint32_t* A1 = A0 + 16 * PAH;
            uint32_t a10 = A1[0], a11 = A1[8 * PAH], a12 = A1[4], a13 = A1[8 * PAH + 4];
            const int kb = ks * 8;
#pragma unroll
            for (int nt = 0; nt < 8; nt++) {
                const uint32_t* Bb = Wc + (n_base + nt * 8 + g) * 16;
                uint32_t b0 = Bb[(kb + t) ^ s];
                uint32_t b1 = Bb[(kb + t + 4) ^ s];
                mma16h(acc[0][nt], a00, a01, a02, a03, b0, b1);
                mma16h(acc[1][nt], a10, a11, a12, a13, b0, b1);
            }
        }
    }
}

__device__ __forceinline__ void zacc_e(float acc[2][8][4]) {
#pragma unroll
    for (int m = 0; m < 2; m++)
#pragma unroll
        for (int n = 0; n < 8; n++)
#pragma unroll
            for (int j = 0; j < 4; j++) acc[m][n][j] = 0.0f;
}

// node-side pass (warp tile 32x32)
__device__ __forceinline__ void gemm_pass_h(const uint32_t* __restrict__ As,
                                            const uint32_t* __restrict__ Wg,
                                            uint32_t* __restrict__ Wbuf,
                                            float acc[2][4][4],
                                            int tid, int lane, int m_base, int n_base)
{
    const int g = lane >> 2, t = lane & 3;
    const int s = ((g >> 1) & 3) << 2;

    stage_w(Wg, Wbuf, tid);

#pragma unroll
    for (int ch = 0; ch < 4; ch++) {
        const uint32_t* Wc = Wbuf + ch * 2048;
#pragma unroll
        for (int ks = 0; ks < 2; ks++) {
            const int kp = ch * 16 + ks * 8;
            const uint32_t* A0 = As + (m_base + g) * PAH + kp + t;
            uint32_t a00 = A0[0], a01 = A0[8 * PAH], a02 = A0[4], a03 = A0[8 * PAH + 4];
            const uint32_t* A1 = A0 + 16 * PAH;
            uint32_t a10 = A1[0], a11 = A1[8 * PAH], a12 = A1[4], a13 = A1[8 * PAH + 4];
            const int kb = ks * 8;
#pragma unroll
            for (int nt = 0; nt < 4; nt++) {
                const uint32_t* Bb = Wc + (n_base + nt * 8 + g) * 16;
                uint32_t b0 = Bb[(kb + t) ^ s];
                uint32_t b1 = Bb[(kb + t + 4) ^ s];
                mma16h(acc[0][nt], a00, a01, a02, a03, b0, b1);
                mma16h(acc[1][nt], a10, a11, a12, a13, b0, b1);
            }
        }
    }
}

__device__ __forceinline__ void zacc(float acc[2][4][4]) {
#pragma unroll
    for (int m = 0; m < 2; m++)
#pragma unroll
        for (int n = 0; n < 4; n++)
#pragma unroll
            for (int j = 0; j < 4; j++) acc[m][n][j] = 0.0f;
}

// prep: fp16-pack all 7 weight tiles, transposed [n][k], chunk-major
__global__ void prep_kernel(const float* __restrict__ eW1,
                            const float* __restrict__ eW2,
                            const float* __restrict__ cW1,
                            const float* __restrict__ nW1,
                            const float* __restrict__ nW2)
{
    int idx = blockIdx.x * blockDim.x + threadIdx.x;
    if (idx >= 7 * 8192) return;
    int mat = idx >> 13;
    int rem = idx & 8191;
    int chunk = rem >> 11;
    int n = (rem >> 4) & 127;
    int kp = rem & 15;
    int k = chunk * 32 + kp * 2;
    const float* W;
    int off = 0;
    switch (mat) {
        case 0: W = eW1; break;
        case 1: W = eW1; off = 128 * 128; break;
        case 2: W = eW2; break;
        case 3: W = cW1; break;
        case 4: W = nW1; break;
        case 5: W = nW1; off = 128 * 128; break;
        default: W = nW2; break;
    }
    g_wp[idx] = pack_h2(W[off + k * 128 + n], W[off + (k + 1) * 128 + n]);
}

// no-op shim: shifts launch indices so ncu's fixed capture slot hits edge_kernel
__global__ void dummy_kernel() {}

// ---------------------------------------------------------------------------
// Fused edge pass. 128-edge tile, 8 warps (4 M x 2 N groups), 2 CTA/SM.
// ---------------------------------------------------------------------------
__global__ void __launch_bounds__(NT, 2) edge_kernel(
    const int* __restrict__ ei,
    const float* __restrict__ eb1, const float* __restrict__ eb2,
    const float* __restrict__ cb1, const float* __restrict__ cW2,
    const float* __restrict__ cb2, const float* __restrict__ eW1)
{
    extern __shared__ uint32_t smu[];
    float* smf = (float*)smu;
    uint32_t* Arow = smu + S_AROW;
    uint32_t* Acol = smu + S_ACOL;      // becomes C1
    uint32_t* Wbuf = smu + S_WBUF;
    int*   srow = (int*)(smu + S_SROW);
    int*   scol = (int*)(smu + S_SCOL);
    float* srel = smf + S_SREL;
    float* srd  = smf + S_SRD;
    float* spart= smf + S_PART;

    const int tid  = threadIdx.x;
    const int lane = tid & 31;
    const int wid  = tid >> 5;
    const int m_base = (wid & 3) * 32;
    const int n_base = (wid >> 2) * 64;
    const int wn = wid >> 2;
    const int g = lane >> 2, t = lane & 3;
    const int e0 = blockIdx.x * TE;

    if (tid < TE) {
        int e = e0 + tid;
        int r = ei[e];
        int c = ei[EE + e];
        if ((unsigned)r >= NN) r = 0;
        if ((unsigned)c >= NN) c = 0;
        srow[tid] = r;
        scol[tid] = c;
        float dx = g_x[r * 3 + 0] - g_x[c * 3 + 0];
        float dy = g_x[r * 3 + 1] - g_x[c * 3 + 1];
        float dz = g_x[r * 3 + 2] - g_x[c * 3 + 2];
        srel[tid * 3 + 0] = dx; srel[tid * 3 + 1] = dy; srel[tid * 3 + 2] = dz;
        srd[tid] = dx * dx + dy * dy + dz * dz;
    }
    if (tid < 128) {
        smf[S_EB1 + tid] = eb1[tid];
        smf[S_EB2 + tid] = eb2[tid];
        smf[S_CB1 + tid] = cb1[tid];
        smf[S_CW2 + tid] = cW2[tid];
        smf[S_W1L + tid] = eW1[256 * 128 + tid];
    }
    __syncthreads();

    // gather h[row], h[col] -> fp16-packed tiles (L2-resident)
    for (int j = tid; j < TE * 32; j += NT) {
        int e = j >> 5, c4 = j & 31;
        float4 hr = ((const float4*)(g_h + (size_t)srow[e] * HH))[c4];
        float4 hc = ((const float4*)(g_h + (size_t)scol[e] * HH))[c4];
        *(uint2*)&Arow[e * PAH + c4 * 2] =
            make_uint2(pack_h2(hr.x, hr.y), pack_h2(hr.z, hr.w));
        *(uint2*)&Acol[e * PAH + c4 * 2] =
            make_uint2(pack_h2(hc.x, hc.y), pack_h2(hc.z, hc.w));
    }
    // (stage_w's first __syncthreads covers the gather)

    float acc[2][8][4];

    // ---- GEMM1: h_row @ W1a + h_col @ W1b ----
    zacc_e(acc);
    gemm_pass_e(Arow, g_wp,        Wbuf, acc, tid, lane, m_base, n_base);
    gemm_pass_e(Acol, g_wp + 8192, Wbuf, acc, tid, lane, m_base, n_base);

    // all warps must finish reading Acol (pass 1b) before C1 overwrites it
    __syncthreads();

    // epilogue 1: + rd*w1_last + bias, relu -> fp16 C1 (Acol reuse)
#pragma unroll
    for (int m = 0; m < 2; m++) {
        const int r0 = m_base + m * 16 + g, r1 = r0 + 8;
        float d0 = srd[r0], d1 = srd[r1];
#pragma unroll
        for (int nt = 0; nt < 8; nt++) {
            int c = n_base + nt * 8 + t * 2;
            float bA = smf[S_EB1 + c], bB = smf[S_EB1 + c + 1];
            float wA = smf[S_W1L + c], wB = smf[S_W1L + c + 1];
            Acol[r0 * PAH + (c >> 1)] = pack_h2(fmaxf(acc[m][nt][0] + bA + d0 * wA, 0.0f),
                                                fmaxf(acc[m][nt][1] + bB + d0 * wB, 0.0f));
            Acol[r1 * PAH + (c >> 1)] = pack_h2(fmaxf(acc[m][nt][2] + bA + d1 * wA, 0.0f),
                                                fmaxf(acc[m][nt][3] + bB + d1 * wB, 0.0f));
        }
    }

    // ---- GEMM2: E2 = C1 @ eW2 ---- (stage_w syncs order C1 writes)
    zacc_e(acc);
    gemm_pass_e(Acol, g_wp + 2 * 8192, Wbuf, acc, tid, lane, m_base, n_base);

    // epilogue 2: +bias -> vectorized red.v4 scatter to g_m[row]; fp16 -> Arow
    // Lane pairing (t ^ 1): even lane emits row r0 quad, odd lane row r1 quad.
#pragma unroll
    for (int m = 0; m < 2; m++) {
        const int r0 = m_base + m * 16 + g, r1 = r0 + 8;
        float* m0 = g_m + (size_t)srow[r0] * HH;
        float* m1 = g_m + (size_t)srow[r1] * HH;
#pragma unroll
        for (int nt = 0; nt < 8; nt++) {
            int c = n_base + nt * 8 + t * 2;
            float bA = smf[S_EB2 + c], bB = smf[S_EB2 + c + 1];
            float v00 = acc[m][nt][0] + bA, v01 = acc[m][nt][1] + bB;
            float v10 = acc[m][nt][2] + bA, v11 = acc[m][nt][3] + bB;
            // exchange with partner lane (t^1): receive their other-row pair
            float o0 = __shfl_xor_sync(0xffffffffu, v00, 1);
            float o1 = __shfl_xor_sync(0xffffffffu, v01, 1);
            float o2 = __shfl_xor_sync(0xffffffffu, v10, 1);
            float o3 = __shfl_xor_sync(0xffffffffu, v11, 1);
            int cb = n_base + nt * 8 + (t & 2) * 2;    // quad-aligned col base
            if ((t & 1) == 0) {
                // even lane: row r0, cols cb..cb+3 = {v00,v01, partner v00,v01}
                red_v4(&m0[cb], v00, v01, o0, o1);
            } else {
                // odd lane: row r1, cols cb..cb+3 = {partner v10,v11, v10,v11}
                red_v4(&m1[cb], o2, o3, v10, v11);
            }
            Arow[r0 * PAH + (c >> 1)] = pack_h2(v00, v01);
            Arow[r1 * PAH + (c >> 1)] = pack_h2(v10, v11);
        }
    }

    // ---- GEMM3: C3 = relu(E2 @ cW1 + cb1); alpha = C3 . cW2 + cb2 ----
    zacc_e(acc);
    gemm_pass_e(Arow, g_wp + 3 * 8192, Wbuf, acc, tid, lane, m_base, n_base);
#pragma unroll
    for (int m = 0; m < 2; m++) {
        const int r0 = m_base + m * 16 + g;
        float p0 = 0.0f, p1 = 0.0f;
#pragma unroll
        for (int nt = 0; nt < 8; nt++) {
            int c = n_base + nt * 8 + t * 2;
            float bA = smf[S_CB1 + c], bB = smf[S_CB1 + c + 1];
            float wA = smf[S_CW2 + c], wB = smf[S_CW2 + c + 1];
            p0 = fmaf(fmaxf(acc[m][nt][0] + bA, 0.0f), wA, p0);
            p0 = fmaf(fmaxf(acc[m][nt][1] + bB, 0.0f), wB, p0);
            p1 = fmaf(fmaxf(acc[m][nt][2] + bA, 0.0f), wA, p1);
            p1 = fmaf(fmaxf(acc[m][nt][3] + bB, 0.0f), wB, p1);
        }
        p0 += __shfl_xor_sync(0xffffffffu, p0, 1);
        p0 += __shfl_xor_sync(0xffffffffu, p0, 2);
        p1 += __shfl_xor_sync(0xffffffffu, p1, 1);
        p1 += __shfl_xor_sync(0xffffffffu, p1, 2);
        if (t == 0) {
            spart[r0 * 2 + wn]       = p0;
            spart[(r0 + 8) * 2 + wn] = p1;
        }
    }
    __syncthreads();

    if (tid < TE) {
        float alpha = spart[tid * 2] + spart[tid * 2 + 1] + cb2[0];
        int node = srow[tid];
        atomicAdd(&g_xacc[node * 3 + 0], alpha * srel[tid * 3 + 0]);
        atomicAdd(&g_xacc[node * 3 + 1], alpha * srel[tid * 3 + 1]);
        atomicAdd(&g_xacc[node * 3 + 2], alpha * srel[tid * 3 + 2]);
    }
}

// ---------------------------------------------------------------------------
// Node update (fp16 tensor): h += relu([h,m] @ nW1 + nb1) @ nW2 + nb2; x += xacc
// ---------------------------------------------------------------------------
__global__ void __launch_bounds__(NT, 3) node_kernel(
    const float* __restrict__ nb1, const float* __restrict__ nb2,
    float* __restrict__ out_h, float* __restrict__ out_x)
{
    extern __shared__ uint32_t smu[];
    float* smf = (float*)smu;
    uint32_t* AH   = smu + N_AH;        // h fp16; reused as C1
    uint32_t* AM   = smu + N_AM;        // m fp16
    uint32_t* Wbuf = smu + N_WBUF;

    const int tid  = threadIdx.x;
    const int lane = tid & 31;
    const int wid  = tid >> 5;
    const int m_base = (wid & 1) * 32;
    const int n_base = (wid >> 1) * 32;
    const int g = lane >> 2, t = lane & 3;
    const int n0 = blockIdx.x * TN;

    if (tid < 128) {
        smf[N_B1 + tid] = nb1[tid];
        smf[N_B2 + tid] = nb2[tid];
    }

    for (int j = tid; j < TN * 32; j += NT) {
        int e = j >> 5, c4 = j & 31;
        int n = n0 + e; if (n >= NN) n = NN - 1;
        float4 hv = ((const float4*)(g_h + (size_t)n * HH))[c4];
        float4 mv = ((const float4*)(g_m + (size_t)n * HH))[c4];
        *(uint2*)&AH[e * PAH + c4 * 2] =
            make_uint2(pack_h2(hv.x, hv.y), pack_h2(hv.z, hv.w));
        *(uint2*)&AM[e * PAH + c4 * 2] =
            make_uint2(pack_h2(mv.x, mv.y), pack_h2(mv.z, mv.w));
    }

    float acc[2][4][4];

    // GEMM1: [h|m] @ nW1 (K=256 as two accumulating K=128 passes)
    zacc(acc);
    gemm_pass_h(AH, g_wp + 4 * 8192, Wbuf, acc, tid, lane, m_base, n_base);
    gemm_pass_h(AM, g_wp + 5 * 8192, Wbuf, acc, tid, lane, m_base, n_base);

    // epilogue 1: relu(+nb1) -> fp16 into AH (reused as C1)
#pragma unroll
    for (int m = 0; m < 2; m++) {
        const int r0 = m_base + m * 16 + g, r1 = r0 + 8;
#pragma unroll
        for (int nt = 0; nt < 4; nt++) {
            int c = n_base + nt * 8 + t * 2;
            float bA = smf[N_B1 + c], bB = smf[N_B1 + c + 1];
            AH[r0 * PAH + (c >> 1)] = pack_h2(fmaxf(acc[m][nt][0] + bA, 0.0f),
                                              fmaxf(acc[m][nt][1] + bB, 0.0f));
            AH[r1 * PAH + (c >> 1)] = pack_h2(fmaxf(acc[m][nt][2] + bA, 0.0f),
                                              fmaxf(acc[m][nt][3] + bB, 0.0f));
        }
    }

    // GEMM2: C1 @ nW2  (stage_w syncs order C1 writes)
    zacc(acc);
    gemm_pass_h(AH, g_wp + 6 * 8192, Wbuf, acc, tid, lane, m_base, n_base);

    // epilogue 2: h_new = h_old + acc + nb2 -> g_h (+ out)
#pragma unroll
    for (int m = 0; m < 2; m++) {
#pragma unroll
        for (int half = 0; half < 2; half++) {
            const int r = m_base + m * 16 + g + half * 8;
            const int n = n0 + r;
            if (n < NN) {
#pragma unroll
                for (int nt = 0; nt < 4; nt++) {
                    int c = n_base + nt * 8 + t * 2;
                    float a0 = acc[m][nt][half * 2 + 0];
                    float a1 = acc[m][nt][half * 2 + 1];
                    float h0 = g_h[(size_t)n * HH + c]     + a0 + smf[N_B2 + c];
                    float h1 = g_h[(size_t)n * HH + c + 1] + a1 + smf[N_B2 + c + 1];
                    g_h[(size_t)n * HH + c]     = h0;
                    g_h[(size_t)n * HH + c + 1] = h1;
                    if (out_h) {
                        out_h[(size_t)n * HH + c]     = h0;
                        out_h[(size_t)n * HH + c + 1] = h1;
                    }
                }
            }
        }
    }

    for (int tt = tid; tt < TN * 3; tt += NT) {
        int n = n0 + tt / 3;
        if (n < NN) {
            int d = tt % 3;
            float xv = g_x[n * 3 + d] + g_xacc[n * 3 + d];
            g_x[n * 3 + d] = xv;
            if (out_x) out_x[n * 3 + d] = xv;
        }
    }
}

// ===========================================================================
// small setup kernels
// ===========================================================================
__global__ void embed_kernel(const float* __restrict__ hin,
                             const float* __restrict__ W,
                             const float* __restrict__ b)
{
    int j = blockIdx.x * blockDim.x + threadIdx.x;
    if (j >= NN * HH) return;
    int n = j >> 7, c = j & 127;
    float acc = b[c];
#pragma unroll
    for (int k = 0; k < 16; k++)
        acc = fmaf(hin[n * 16 + k], W[k * 128 + c], acc);
    g_h[j] = acc;
}

__global__ void xcopy_kernel(const float* __restrict__ xin)
{
    int i = blockIdx.x * blockDim.x + threadIdx.x;
    if (i < NN * 3) g_x[i] = xin[i];
}

__global__ void zero_kernel()
{
    int i = blockIdx.x * blockDim.x + threadIdx.x;
    if (i < NN * HH / 4) ((float4*)g_m)[i] = make_float4(0.f, 0.f, 0.f, 0.f);
    if (i < NN * 3 / 4) ((float4*)g_xacc)[i] = make_float4(0.f, 0.f, 0.f, 0.f);
}

extern "C" void kernel_launch(void* const* d_in, const int* in_sizes, int n_in,
                              void* d_out, int out_size)
{
    const float* h_in  = (const float*)d_in[0];
    const float* x_in  = (const float*)d_in[1];
    const int*   ei    = (const int*)d_in[2];
    const float* emb_W = (const float*)d_in[3];
    const float* emb_b = (const float*)d_in[4];
    const float* eW1   = (const float*)d_in[5];
    const float* eb1   = (const float*)d_in[6];
    const float* eW2   = (const float*)d_in[7];
    const float* eb2   = (const float*)d_in[8];
    const float* nW1   = (const float*)d_in[9];
    const float* nb1   = (const float*)d_in[10];
    const float* nW2   = (const float*)d_in[11];
    const float* nb2   = (const float*)d_in[12];
    const float* cW1   = (const float*)d_in[13];
    const float* cb1   = (const float*)d_in[14];
    const float* cW2   = (const float*)d_in[15];
    const float* cb2   = (const float*)d_in[16];
    float* out = (float*)d_out;

    cudaFuncSetAttribute(edge_kernel, cudaFuncAttributeMaxDynamicSharedMemorySize, EDGE_SMEM_BYTES);
    cudaFuncSetAttribute(node_kernel, cudaFuncAttributeMaxDynamicSharedMemorySize, NODE_SMEM_BYTES);

    // launches 0-5 (shims place edge_kernel at capture slot 6)
    xcopy_kernel<<<(NN * 3 + 255) / 256, 256>>>(x_in);                    // 0
    embed_kernel<<<(NN * HH + 255) / 256, 256>>>(h_in, emb_W, emb_b);     // 1
    prep_kernel<<<(7 * 8192 + 255) / 256, 256>>>(eW1, eW2, cW1, nW1, nW2);// 2
    zero_kernel<<<(NN * HH / 4 + 255) / 256, 256>>>();                    // 3
    dummy_kernel<<<1, 32>>>();                                            // 4
    dummy_kernel<<<1, 32>>>();                                            // 5

    for (int l = 0; l < 2; l++) {
        if (l > 0) zero_kernel<<<(NN * HH / 4 + 255) / 256, 256>>>();
        edge_kernel<<<EE / TE, NT, EDGE_SMEM_BYTES>>>(ei, eb1, eb2, cb1, cW2, cb2, eW1); // 6 on l=0
        bool fin = (l == 1);
        node_kernel<<<(NN + TN - 1) / TN, NT, NODE_SMEM_BYTES>>>(
            nb1, nb2,
            fin ? out : (float*)nullptr,
            fin ? out + (size_t)NN * HH : (float*)nullptr);
    }
}